// round 15
// baseline (speedup 1.0000x reference)
#include <cuda_runtime.h>
#include <cuda_bf16.h>
#include <math.h>
#include <stdint.h>

#define NN 50000
#define EE 800000
#define FF 256
#define LL 4
#define NEG_SLOPE 0.2f
#define BNEPS 1e-5f

// ---------------- scratch (static device globals: no runtime allocation) ----
__device__ float g_etmp[(size_t)EE * FF];   // v = e@We + hWs[src] + hWd[dst]
__device__ float g_hWs[(size_t)NN * FF];
__device__ float g_hWd[(size_t)NN * FF];
__device__ float g_hWf[(size_t)NN * FF];
__device__ float g_hWb[(size_t)NN * FF];
__device__ float g_htmp[(size_t)NN * FF];
__device__ float g_logf[EE];
__device__ float g_logb[EE];
__device__ float g_statsE[2][2 * FF];       // double-buffered by layer parity
__device__ float g_statsH[2 * FF];
// bf16 hi/lo split state (e lives ONLY here between layers)
__device__ __nv_bfloat16 g_ehi[(size_t)EE * FF];
__device__ __nv_bfloat16 g_elo[(size_t)EE * FF];
__device__ __nv_bfloat16 g_hhi[(size_t)NN * FF];
__device__ __nv_bfloat16 g_hlo[(size_t)NN * FF];
// transposed bf16 hi/lo weights: [6 types][LL][256n][256k]
__device__ __nv_bfloat16 g_wthi[(size_t)6 * LL * FF * FF];
__device__ __nv_bfloat16 g_wtlo[(size_t)6 * LL * FF * FF];
// CSR (built once per launch; graph static across layers)
__device__ int g_degI[NN];
__device__ int g_degO[NN];
__device__ int g_offI[NN + 1];
__device__ int g_offO[NN + 1];
__device__ int g_curI[NN];
__device__ int g_curO[NN];
__device__ int g_inEid[EE];
__device__ int g_inSrc[EE];
__device__ int g_outEid[EE];
__device__ int g_outDst[EE];

// ---------------- small helpers -------------------------------------------
__device__ __forceinline__ void ld8(const float* p, float* v) {
    float4 a = *(const float4*)p;
    float4 b = *(const float4*)(p + 4);
    v[0] = a.x; v[1] = a.y; v[2] = a.z; v[3] = a.w;
    v[4] = b.x; v[5] = b.y; v[6] = b.z; v[7] = b.w;
}
__device__ __forceinline__ void st8(float* p, const float* v) {
    *(float4*)p       = make_float4(v[0], v[1], v[2], v[3]);
    *(float4*)(p + 4) = make_float4(v[4], v[5], v[6], v[7]);
}
__device__ __forceinline__ void split_pack(const float* v, uint4* ph, uint4* pl) {
    unsigned hw[4], lw[4];
#pragma unroll
    for (int j = 0; j < 4; j++) {
        __nv_bfloat16 h0 = __float2bfloat16(v[2 * j]);
        __nv_bfloat16 h1 = __float2bfloat16(v[2 * j + 1]);
        __nv_bfloat16 l0 = __float2bfloat16(v[2 * j]     - __bfloat162float(h0));
        __nv_bfloat16 l1 = __float2bfloat16(v[2 * j + 1] - __bfloat162float(h1));
        hw[j] = (unsigned)__bfloat16_as_ushort(h0) | ((unsigned)__bfloat16_as_ushort(h1) << 16);
        lw[j] = (unsigned)__bfloat16_as_ushort(l0) | ((unsigned)__bfloat16_as_ushort(l1) << 16);
    }
    *ph = make_uint4(hw[0], hw[1], hw[2], hw[3]);
    *pl = make_uint4(lw[0], lw[1], lw[2], lw[3]);
}
__device__ __forceinline__ void unpack8(uint4 uh, uint4 ul, float* e) {
    unsigned hw[4] = {uh.x, uh.y, uh.z, uh.w};
    unsigned lw[4] = {ul.x, ul.y, ul.z, ul.w};
#pragma unroll
    for (int j = 0; j < 4; j++) {
        __nv_bfloat162 h2 = *reinterpret_cast<__nv_bfloat162*>(&hw[j]);
        __nv_bfloat162 l2 = *reinterpret_cast<__nv_bfloat162*>(&lw[j]);
        e[2 * j]     = __bfloat162float(h2.x) + __bfloat162float(l2.x);
        e[2 * j + 1] = __bfloat162float(h2.y) + __bfloat162float(l2.y);
    }
}

__global__ void fill_u(unsigned* p, size_t n, unsigned v) {
    for (size_t i = (size_t)blockIdx.x * blockDim.x + threadIdx.x; i < n;
         i += (size_t)gridDim.x * blockDim.x) p[i] = v;
}
// per-layer init: logf/logb = 0, stats(parity) = 0
__global__ void init_layer(float* logf, float* logb, float* stE, float* stH) {
    for (size_t i = (size_t)blockIdx.x * blockDim.x + threadIdx.x; i < EE;
         i += (size_t)gridDim.x * blockDim.x) {
        logf[i] = 0.f; logb[i] = 0.f;
        if (i < 2 * FF) { stE[i] = 0.f; stH[i] = 0.f; }
    }
}

// ---------------- CSR build -------------------------------------------------
__global__ void hist_kernel(const int* __restrict__ src, const int* __restrict__ dst,
                            int* dI, int* dO) {
    for (int e = blockIdx.x * blockDim.x + threadIdx.x; e < EE;
         e += gridDim.x * blockDim.x) {
        atomicAdd(&dI[dst[e]], 1);
        atomicAdd(&dO[src[e]], 1);
    }
}
__global__ void scan_kernel(const int* __restrict__ dI, const int* __restrict__ dO,
                            int* offI, int* offO, int* curI, int* curO) {
    __shared__ int bufI[1024], bufO[1024];
    __shared__ int carryI, carryO;
    int tid = threadIdx.x;
    if (tid == 0) { carryI = 0; carryO = 0; }
    __syncthreads();
    for (int base = 0; base < NN; base += 1024) {
        int i = base + tid;
        int vI = (i < NN) ? dI[i] : 0;
        int vO = (i < NN) ? dO[i] : 0;
        bufI[tid] = vI; bufO[tid] = vO;
        __syncthreads();
        for (int off = 1; off < 1024; off <<= 1) {
            int aI = (tid >= off) ? bufI[tid - off] : 0;
            int aO = (tid >= off) ? bufO[tid - off] : 0;
            __syncthreads();
            bufI[tid] += aI; bufO[tid] += aO;
            __syncthreads();
        }
        if (i < NN) {
            int exI = carryI + bufI[tid] - vI;
            int exO = carryO + bufO[tid] - vO;
            offI[i] = exI; offO[i] = exO;
            curI[i] = exI; curO[i] = exO;
        }
        __syncthreads();
        if (tid == 1023) { carryI += bufI[1023]; carryO += bufO[1023]; }
        __syncthreads();
    }
    if (tid == 0) { offI[NN] = carryI; offO[NN] = carryO; }
}
__global__ void scatter_kernel(const int* __restrict__ src, const int* __restrict__ dst,
                               int* curI, int* curO,
                               int* inEid, int* inSrc, int* outEid, int* outDst) {
    for (int e = blockIdx.x * blockDim.x + threadIdx.x; e < EE;
         e += gridDim.x * blockDim.x) {
        int s = src[e], d = dst[e];
        int p = atomicAdd(&curI[d], 1);
        inEid[p] = e; inSrc[p] = s;
        int q = atomicAdd(&curO[s], 1);
        outEid[q] = e; outDst[q] = d;
    }
}

// ---------------- mma.sync primitives --------------------------------------
__device__ __forceinline__ uint32_t s2u(const void* p) {
    uint32_t a;
    asm("{ .reg .u64 t; cvta.to.shared.u64 t, %1; cvt.u32.u64 %0, t; }"
        : "=r"(a) : "l"(p));
    return a;
}
__device__ __forceinline__ void cpa16(uint32_t s, const void* g) {
    asm volatile("cp.async.cg.shared.global [%0], [%1], 16;"
                 :: "r"(s), "l"(g) : "memory");
}
__device__ __forceinline__ void cp_commit() {
    asm volatile("cp.async.commit_group;" ::: "memory");
}
template <int N>
__device__ __forceinline__ void cp_wait() {
    asm volatile("cp.async.wait_group %0;" :: "n"(N) : "memory");
}
__device__ __forceinline__ void ldm4(uint32_t* r, uint32_t a) {
    asm volatile("ldmatrix.sync.aligned.m8n8.x4.shared.b16 {%0,%1,%2,%3}, [%4];"
                 : "=r"(r[0]), "=r"(r[1]), "=r"(r[2]), "=r"(r[3]) : "r"(a));
}
__device__ __forceinline__ void mma16816(float* d, const uint32_t* a, const uint32_t* b) {
    asm volatile(
        "mma.sync.aligned.m16n8k16.row.col.f32.bf16.bf16.f32 "
        "{%0,%1,%2,%3}, {%4,%5,%6,%7}, {%8,%9}, {%0,%1,%2,%3};"
        : "+f"(d[0]), "+f"(d[1]), "+f"(d[2]), "+f"(d[3])
        : "r"(a[0]), "r"(a[1]), "r"(a[2]), "r"(a[3]), "r"(b[0]), "r"(b[1]));
}

// ---------------- tensor-core GEMM core ------------------------------------
#define BK 32
#define ROWB 80
#define TILEB (128 * ROWB)
#define STAGEB (4 * TILEB)
#define GEMM_SMEM (2 * STAGEB)

template <bool EDGE>
__device__ __forceinline__ void gemm_core(
    const __nv_bfloat16* __restrict__ Ahi, const __nv_bfloat16* __restrict__ Alo,
    const __nv_bfloat16* __restrict__ Bhi, const __nv_bfloat16* __restrict__ Blo,
    float* __restrict__ C, int M, int row0, int col0, char* sm,
    const int* __restrict__ src, const int* __restrict__ dst,
    const float* __restrict__ hWs, const float* __restrict__ hWd,
    const float* __restrict__ af, const float* __restrict__ ab,
    float* __restrict__ logf, float* __restrict__ logb,
    float* __restrict__ stats)
{
    uint32_t sb = s2u(sm);
    int tid = threadIdx.x;
    int wid = tid >> 5, lane = tid & 31;
    int wm = (wid >> 2) * 64;
    int wn = (wid & 3) * 32;

    float acc[4][4][4];
#pragma unroll
    for (int i = 0; i < 4; i++)
#pragma unroll
        for (int j = 0; j < 4; j++)
#pragma unroll
            for (int q = 0; q < 4; q++) acc[i][j][q] = 0.f;

    int c0 = tid, c1 = tid + 256;
    int r0c = c0 >> 2, cc0 = c0 & 3;
    int r1c = c1 >> 2, cc1 = c1 & 3;
    int ga0 = min(row0 + r0c, M - 1);
    int ga1 = min(row0 + r1c, M - 1);
    int gb0 = col0 + r0c;
    int gb1 = col0 + r1c;
    uint32_t so0 = (uint32_t)(r0c * ROWB + cc0 * 16);
    uint32_t so1 = (uint32_t)(r1c * ROWB + cc1 * 16);

#define PREFETCH(ks, buf) do {                                                   \
        int k0 = (ks) * BK;                                                      \
        uint32_t s0 = sb + (buf) * STAGEB + so0;                                 \
        uint32_t s1 = sb + (buf) * STAGEB + so1;                                 \
        cpa16(s0,              Ahi + (size_t)ga0 * FF + k0 + cc0 * 8);           \
        cpa16(s0 + TILEB,      Alo + (size_t)ga0 * FF + k0 + cc0 * 8);           \
        cpa16(s0 + 2 * TILEB,  Bhi + (size_t)gb0 * FF + k0 + cc0 * 8);           \
        cpa16(s0 + 3 * TILEB,  Blo + (size_t)gb0 * FF + k0 + cc0 * 8);           \
        cpa16(s1,              Ahi + (size_t)ga1 * FF + k0 + cc1 * 8);           \
        cpa16(s1 + TILEB,      Alo + (size_t)ga1 * FF + k0 + cc1 * 8);           \
        cpa16(s1 + 2 * TILEB,  Bhi + (size_t)gb1 * FF + k0 + cc1 * 8);           \
        cpa16(s1 + 3 * TILEB,  Blo + (size_t)gb1 * FF + k0 + cc1 * 8);           \
        cp_commit();                                                             \
    } while (0)

    int a_row  = wm + (lane & 15);
    int a_cch  = (lane >> 4) & 1;
    int b_row  = wn + (lane & 7) + ((lane >> 4) & 1) * 8;
    int b_cch  = ((lane >> 3) & 1) * 8;

    PREFETCH(0, 0);

    for (int ks = 0; ks < FF / BK; ks++) {
        int buf = ks & 1;
        if (ks < FF / BK - 1) { PREFETCH(ks + 1, buf ^ 1); cp_wait<1>(); }
        else                  { cp_wait<0>(); }
        __syncthreads();

        uint32_t base = sb + buf * STAGEB;
#pragma unroll
        for (int kc = 0; kc < 2; kc++) {
            int klocal = kc * 16;
            uint32_t ah[4][4], al[4][4];
#pragma unroll
            for (int i = 0; i < 4; i++) {
                uint32_t ad = base + (uint32_t)((a_row + i * 16) * ROWB
                                                + (klocal + a_cch * 8) * 2);
                ldm4(ah[i], ad);
                ldm4(al[i], ad + TILEB);
            }
            uint32_t bh[2][4], bl[2][4];
#pragma unroll
            for (int jj = 0; jj < 2; jj++) {
                uint32_t bd = base + 2 * TILEB
                            + (uint32_t)((b_row + jj * 16) * ROWB
                                         + (klocal + b_cch) * 2);
                ldm4(bh[jj], bd);
                ldm4(bl[jj], bd + TILEB);
            }
#pragma unroll
            for (int i = 0; i < 4; i++)
#pragma unroll
                for (int j = 0; j < 4; j++)
                    mma16816(acc[i][j], ah[i], &bh[j >> 1][(j & 1) * 2]);
#pragma unroll
            for (int i = 0; i < 4; i++)
#pragma unroll
                for (int j = 0; j < 4; j++)
                    mma16816(acc[i][j], ah[i], &bl[j >> 1][(j & 1) * 2]);
#pragma unroll
            for (int i = 0; i < 4; i++)
#pragma unroll
                for (int j = 0; j < 4; j++)
                    mma16816(acc[i][j], al[i], &bh[j >> 1][(j & 1) * 2]);
        }
        __syncthreads();
    }

    if (!EDGE) {
#pragma unroll
        for (int i = 0; i < 4; i++) {
            int r = row0 + wm + i * 16 + (lane >> 2);
            int cbase = col0 + wn + (lane & 3) * 2;
            if (r < M) {
                float* cp = C + (size_t)r * FF + cbase;
#pragma unroll
                for (int j = 0; j < 4; j++)
                    *(float2*)(cp + j * 8) = make_float2(acc[i][j][0], acc[i][j][1]);
            }
            if (r + 8 < M) {
                float* cp = C + (size_t)(r + 8) * FF + cbase;
#pragma unroll
                for (int j = 0; j < 4; j++)
                    *(float2*)(cp + j * 8) = make_float2(acc[i][j][2], acc[i][j][3]);
            }
        }
    } else {
        float s8[8], q8[8];
#pragma unroll
        for (int k = 0; k < 8; k++) { s8[k] = 0.f; q8[k] = 0.f; }
        int cbase = col0 + wn + (lane & 3) * 2;
#pragma unroll
        for (int i = 0; i < 4; i++) {
            int r  = row0 + wm + i * 16 + (lane >> 2);
            int r2 = r + 8;
            int sA = src[r],  dA = dst[r];
            int sB = src[r2], dB = dst[r2];
            float lf1 = 0.f, lb1 = 0.f, lf2 = 0.f, lb2 = 0.f;
#pragma unroll
            for (int j = 0; j < 4; j++) {
                int c = cbase + j * 8;
                float2 afv = *(const float2*)(af + c);
                float2 abv = *(const float2*)(ab + c);
                float2 xs = *(const float2*)(hWs + (size_t)sA * FF + c);
                float2 yd = *(const float2*)(hWd + (size_t)dA * FF + c);
                float v0 = acc[i][j][0] + xs.x + yd.x;
                float v1 = acc[i][j][1] + xs.y + yd.y;
                *(float2*)(C + (size_t)r * FF + c) = make_float2(v0, v1);
                lf1 += v0 * afv.x + v1 * afv.y;
                lb1 += v0 * abv.x + v1 * abv.y;
                s8[2 * j] += v0;       s8[2 * j + 1] += v1;
                q8[2 * j] += v0 * v0;  q8[2 * j + 1] += v1 * v1;
                float2 xs2 = *(const float2*)(hWs + (size_t)sB * FF + c);
                float2 yd2 = *(const float2*)(hWd + (size_t)dB * FF + c);
                float w0 = acc[i][j][2] + xs2.x + yd2.x;
                float w1 = acc[i][j][3] + xs2.y + yd2.y;
                *(float2*)(C + (size_t)r2 * FF + c) = make_float2(w0, w1);
                lf2 += w0 * afv.x + w1 * afv.y;
                lb2 += w0 * abv.x + w1 * abv.y;
                s8[2 * j] += w0;       s8[2 * j + 1] += w1;
                q8[2 * j] += w0 * w0;  q8[2 * j + 1] += w1 * w1;
            }
#pragma unroll
            for (int o = 1; o <= 2; o <<= 1) {
                lf1 += __shfl_xor_sync(0xffffffffu, lf1, o);
                lb1 += __shfl_xor_sync(0xffffffffu, lb1, o);
                lf2 += __shfl_xor_sync(0xffffffffu, lf2, o);
                lb2 += __shfl_xor_sync(0xffffffffu, lb2, o);
            }
            if ((lane & 3) == 0) {
                atomicAdd(&logf[r],  lf1);
                atomicAdd(&logb[r],  lb1);
                atomicAdd(&logf[r2], lf2);
                atomicAdd(&logb[r2], lb2);
            }
        }
#pragma unroll
        for (int k = 0; k < 8; k++) {
#pragma unroll
            for (int o = 4; o <= 16; o <<= 1) {
                s8[k] += __shfl_xor_sync(0xffffffffu, s8[k], o);
                q8[k] += __shfl_xor_sync(0xffffffffu, q8[k], o);
            }
        }
        if (lane < 4) {
            int cb = col0 + wn + lane * 2;
#pragma unroll
            for (int j = 0; j < 4; j++) {
                atomicAdd(&stats[cb + j * 8],          s8[2 * j]);
                atomicAdd(&stats[cb + j * 8 + 1],      s8[2 * j + 1]);
                atomicAdd(&stats[FF + cb + j * 8],     q8[2 * j]);
                atomicAdd(&stats[FF + cb + j * 8 + 1], q8[2 * j + 1]);
            }
        }
    }
#undef PREFETCH
}

__global__ void __launch_bounds__(256, 1)
gemm_edge(const __nv_bfloat16* __restrict__ Ahi, const __nv_bfloat16* __restrict__ Alo,
          const __nv_bfloat16* __restrict__ Bhi, const __nv_bfloat16* __restrict__ Blo,
          float* __restrict__ C,
          const int* __restrict__ src, const int* __restrict__ dst,
          const float* __restrict__ hWs, const float* __restrict__ hWd,
          const float* __restrict__ af, const float* __restrict__ ab,
          float* __restrict__ logf, float* __restrict__ logb,
          float* __restrict__ stats)
{
    extern __shared__ __align__(128) char sm[];
    gemm_core<true>(Ahi, Alo, Bhi, Blo, C, EE, blockIdx.y * 128, blockIdx.x * 128,
                    sm, src, dst, hWs, hWd, af, ab, logf, logb, stats);
}

// node GEMM, 2 types (Ws, Wd) — critical path
__global__ void __launch_bounds__(256, 1)
gemm_mma_multi2(const __nv_bfloat16* __restrict__ Ahi, const __nv_bfloat16* __restrict__ Alo,
                const __nv_bfloat16* __restrict__ Bhi0, const __nv_bfloat16* __restrict__ Blo0,
                float* C0, float* C1)
{
    extern __shared__ __align__(128) char sm[];
    int t = blockIdx.x >> 1;
    int col0 = (blockIdx.x & 1) * 128;
    size_t ws = (size_t)t * LL * FF * FF;
    float* C = (t == 0) ? C0 : C1;
    gemm_core<false>(Ahi, Alo, Bhi0 + ws, Blo0 + ws, C, NN, blockIdx.y * 128, col0,
                     sm, nullptr, nullptr, nullptr, nullptr, nullptr, nullptr,
                     nullptr, nullptr, nullptr);
}

// node GEMM, 3 types (Wself, Wf, Wb) — side stream, overlaps gemm_edge
__global__ void __launch_bounds__(256, 1)
gemm_mma_multi3(const __nv_bfloat16* __restrict__ Ahi, const __nv_bfloat16* __restrict__ Alo,
                const __nv_bfloat16* __restrict__ Bhi0, const __nv_bfloat16* __restrict__ Blo0,
                float* C0, float* C1, float* C2)
{
    extern __shared__ __align__(128) char sm[];
    int t = blockIdx.x >> 1;
    int col0 = (blockIdx.x & 1) * 128;
    size_t ws = (size_t)t * LL * FF * FF;
    float* C = (t == 0) ? C0 : (t == 1) ? C1 : C2;
    gemm_core<false>(Ahi, Alo, Bhi0 + ws, Blo0 + ws, C, NN, blockIdx.y * 128, col0,
                     sm, nullptr, nullptr, nullptr, nullptr, nullptr, nullptr,
                     nullptr, nullptr, nullptr);
}

// ---------------- weight transpose + bf16 split (all 6 types, one launch) ---
__global__ void prep_w_all(const float* W0, const float* W1, const float* W2,
                           const float* W3, const float* W4, const float* W5,
                           __nv_bfloat16* __restrict__ hi, __nv_bfloat16* __restrict__ lo)
{
    int t   = blockIdx.x >> 10;
    int bl  = blockIdx.x & 1023;
    int l   = bl >> 8;
    int i   = (bl & 255) * 256 + threadIdx.x;
    int n = i >> 8, k = i & 255;
    const float* W = (t == 0) ? W0 : (t == 1) ? W1 : (t == 2) ? W2
                   : (t == 3) ? W3 : (t == 4) ? W4 : W5;
    size_t off = ((size_t)t * LL + l) * FF * FF;
    float w = W[(size_t)l * FF * FF + (size_t)k * FF + n];
    __nv_bfloat16 h = __float2bfloat16(w);
    hi[off + i] = h;
    lo[off + i] = __float2bfloat16(w - __bfloat162float(h));
}

// ---------------- fp32 -> bf16 hi/lo split (bulk) --------------------------
__global__ void split8(const float* __restrict__ x,
                       __nv_bfloat16* __restrict__ hi, __nv_bfloat16* __restrict__ lo,
                       size_t n8)
{
    for (size_t i = (size_t)blockIdx.x * blockDim.x + threadIdx.x; i < n8;
         i += (size_t)gridDim.x * blockDim.x) {
        float v[8];
        ld8(x + i * 8, v);
        uint4 uh, ul;
        split_pack(v, &uh, &ul);
        *(uint4*)(hi + i * 8) = uh;
        *(uint4*)(lo + i * 8) = ul;
    }
}

// ---------------- BN finalize ----------------------------------------------
__global__ void bnfin_kernel(float* stats, float inv_cnt) {
    int f = threadIdx.x;
    float mu  = stats[f] * inv_cnt;
    float var = stats[FF + f] * inv_cnt - mu * mu;
    stats[f]      = mu;
    stats[FF + f] = rsqrtf(var + BNEPS);
}

// ---------------- edge pass B: pure streaming -------------------------------
__global__ void __launch_bounds__(256)
edgeB_kernel(const float* __restrict__ etmp,
             __nv_bfloat16* __restrict__ ehi, __nv_bfloat16* __restrict__ elo,
             float* __restrict__ e_out,
             const float* __restrict__ stats,
             const float* __restrict__ ge, const float* __restrict__ be,
             int finalL)
{
    size_t i = (size_t)blockIdx.x * blockDim.x + threadIdx.x;
    const size_t NV = (size_t)EE * FF / 8;
    if (i >= NV) return;
    int c = ((int)i & 31) * 8;
    float t[8], ein[8], o[8];
    ld8(etmp + i * 8, t);
    uint4 uh = *(const uint4*)(ehi + i * 8);
    uint4 ul = *(const uint4*)(elo + i * 8);
    unpack8(uh, ul, ein);
#pragma unroll
    for (int j = 0; j < 8; j++) {
        float bn = (t[j] - stats[c + j]) * stats[FF + c + j] * ge[c + j] + be[c + j];
        o[j] = ein[j] + (bn > 0.f ? bn : 0.f);
    }
    if (finalL) {
        st8(e_out + i * 8, o);
    } else {
        uint4 nh, nl;
        split_pack(o, &nh, &nl);
        *(uint4*)(ehi + i * 8) = nh;
        *(uint4*)(elo + i * 8) = nl;
    }
}

// ---------------- node merge: local segment-max + gather aggregation --------
// warp per node; leaky + max computed locally (edgeLog kernel eliminated).
__global__ void __launch_bounds__(256)
nodeMerge_kernel(float* __restrict__ htmp,
                 const float* __restrict__ hWf, const float* __restrict__ hWb,
                 const float* __restrict__ logf, const float* __restrict__ logb,
                 const int* __restrict__ offI, const int* __restrict__ inEid,
                 const int* __restrict__ inSrc,
                 const int* __restrict__ offO, const int* __restrict__ outEid,
                 const int* __restrict__ outDst,
                 float* __restrict__ stats)
{
    int lane = threadIdx.x & 31;
    int gw = (blockIdx.x * blockDim.x + threadIdx.x) >> 5;
    int nw = (gridDim.x * blockDim.x) >> 5;
    int fb = lane * 8;

    float s[8], sq[8];
#pragma unroll
    for (int j = 0; j < 8; j++) { s[j] = 0.f; sq[j] = 0.f; }

    for (int n = gw; n < NN; n += nw) {
        // ---- forward: edges into n ----
        float accf[8];
#pragma unroll
        for (int j = 0; j < 8; j++) accf[j] = 0.f;
        float denf = 0.f;
        {
            int b0 = offI[n], b1 = offI[n + 1];
            // pass 1: local segment max (leaky applied on the fly)
            float mn = -1e30f;
            for (int k = b0 + lane; k < b1; k += 32) {
                float r = logf[inEid[k]];
                r = r > 0.f ? r : NEG_SLOPE * r;
                mn = fmaxf(mn, r);
            }
#pragma unroll
            for (int o = 16; o > 0; o >>= 1)
                mn = fmaxf(mn, __shfl_xor_sync(0xffffffffu, mn, o));
            // pass 2: exp + weighted accumulate
            for (int cb = b0; cb < b1; cb += 32) {
                int cnt = min(32, b1 - cb);
                float ex = 0.f; int si = 0;
                if (lane < cnt) {
                    int k = cb + lane;
                    si = inSrc[k];
                    float r = logf[inEid[k]];
                    r = r > 0.f ? r : NEG_SLOPE * r;
                    ex = expf(r - mn);
                }
                for (int j = 0; j < cnt; j++) {
                    float e  = __shfl_sync(0xffffffffu, ex, j);
                    int   s_ = __shfl_sync(0xffffffffu, si, j);
                    float w[8];
                    ld8(hWf + (size_t)s_ * FF + fb, w);
                    denf += e;
#pragma unroll
                    for (int q = 0; q < 8; q++) accf[q] += e * w[q];
                }
            }
        }
        // ---- backward: edges out of n ----
        float accb[8];
#pragma unroll
        for (int j = 0; j < 8; j++) accb[j] = 0.f;
        float denb = 0.f;
        {
            int b0 = offO[n], b1 = offO[n + 1];
            float mn = -1e30f;
            for (int k = b0 + lane; k < b1; k += 32) {
                float r = logb[outEid[k]];
                r = r > 0.f ? r : NEG_SLOPE * r;
                mn = fmaxf(mn, r);
            }
#pragma unroll
            for (int o = 16; o > 0; o >>= 1)
                mn = fmaxf(mn, __shfl_xor_sync(0xffffffffu, mn, o));
            for (int cb = b0; cb < b1; cb += 32) {
                int cnt = min(32, b1 - cb);
                float ex = 0.f; int di = 0;
                if (lane < cnt) {
                    int k = cb + lane;
                    di = outDst[k];
                    float r = logb[outEid[k]];
                    r = r > 0.f ? r : NEG_SLOPE * r;
                    ex = expf(r - mn);
                }
                for (int j = 0; j < cnt; j++) {
                    float e  = __shfl_sync(0xffffffffu, ex, j);
                    int   d_ = __shfl_sync(0xffffffffu, di, j);
                    float w[8];
                    ld8(hWb + (size_t)d_ * FF + fb, w);
                    denb += e;
#pragma unroll
                    for (int q = 0; q < 8; q++) accb[q] += e * w[q];
                }
            }
        }
        float rf = 1.f / (denf + 1e-9f);
        float rb = 1.f / (denb + 1e-9f);
        float v[8];
        float* ph = htmp + (size_t)n * FF + fb;
        ld8(ph, v);
#pragma unroll
        for (int j = 0; j < 8; j++) {
            v[j] = v[j] + accf[j] * rf + accb[j] * rb;
            s[j]  += v[j];
            sq[j] += v[j] * v[j];
        }
        st8(ph, v);
    }
#pragma unroll
    for (int j = 0; j < 8; j++) {
        atomicAdd(&stats[fb + j], s[j]);
        atomicAdd(&stats[FF + fb + j], sq[j]);
    }
}

// ---------------- node pass B ----------------------------------------------
__global__ void __launch_bounds__(256)
nodeB_kernel(const float* __restrict__ htmp, const float* __restrict__ h_in,
             float* __restrict__ h_out, const float* __restrict__ stats,
             const float* __restrict__ gh, const float* __restrict__ bh,
             __nv_bfloat16* __restrict__ hhi, __nv_bfloat16* __restrict__ hlo,
             int wsplit)
{
    int i = blockIdx.x * blockDim.x + threadIdx.x;
    const int NV = NN * FF / 8;
    if (i >= NV) return;
    int c = (i & 31) * 8;
    float t[8], hv[8], o[8];
    ld8(htmp + (size_t)i * 8, t);
    ld8(h_in + (size_t)i * 8, hv);
#pragma unroll
    for (int j = 0; j < 8; j++) {
        float bn = (t[j] - stats[c + j]) * stats[FF + c + j] * gh[c + j] + bh[c + j];
        o[j] = hv[j] + (bn > 0.f ? bn : 0.f);
    }
    st8(h_out + (size_t)i * 8, o);
    if (wsplit) {
        uint4 uh, ul;
        split_pack(o, &uh, &ul);
        *(uint4*)(hhi + (size_t)i * 8) = uh;
        *(uint4*)(hlo + (size_t)i * 8) = ul;
    }
}

// ---------------- launch ---------------------------------------------------
extern "C" void kernel_launch(void* const* d_in, const int* in_sizes, int n_in,
                              void* d_out, int out_size)
{
    (void)in_sizes; (void)n_in; (void)out_size;
    const float* h0    = (const float*)d_in[0];
    const float* e0    = (const float*)d_in[1];
    const int*   src   = (const int*)d_in[2];
    const int*   dst   = (const int*)d_in[3];
    const float* We    = (const float*)d_in[4];
    const float* Ws    = (const float*)d_in[5];
    const float* Wd    = (const float*)d_in[6];
    const float* Wself = (const float*)d_in[7];
    const float* Wf    = (const float*)d_in[8];
    const float* Wb    = (const float*)d_in[9];
    const float* att_f = (const float*)d_in[10];
    const float* att_b = (const float*)d_in[11];
    const float* g_e   = (const float*)d_in[12];
    const float* b_e   = (const float*)d_in[13];
    const float* g_h   = (const float*)d_in[14];
    const float* b_h   = (const float*)d_in[15];

    float* outh = (float*)d_out;
    float* oute = outh + (size_t)NN * FF;

    float *etmp, *hWs, *hWd, *hWf, *hWb, *htmp;
    float *logf, *logb, *stE, *stH;
    __nv_bfloat16 *ehi, *elo, *hhi, *hlo, *wthi, *wtlo;
    int *degI, *degO, *offI, *offO, *curI, *curO, *inEid, *inSrc, *outEid, *outDst;
    cudaGetSymbolAddress((void**)&etmp, g_etmp);
    cudaGetSymbolAddress((void**)&hWs,  g_hWs);
    cudaGetSymbolAddress((void**)&hWd,  g_hWd);
    cudaGetSymbolAddress((void**)&hWf,  g_hWf);
    cudaGetSymbolAddress((void**)&hWb,  g_hWb);
    cudaGetSymbolAddress((void**)&htmp, g_htmp);
    cudaGetSymbolAddress((void**)&logf, g_logf);
    cudaGetSymbolAddress((void**)&logb, g_logb);
    cudaGetSymbolAddress((void**)&stE,  g_statsE);
    cudaGetSymbolAddress((void**)&stH,  g_statsH);
    cudaGetSymbolAddress((void**)&ehi,  g_ehi);
    cudaGetSymbolAddress((void**)&elo,  g_elo);
    cudaGetSymbolAddress((void**)&hhi,  g_hhi);
    cudaGetSymbolAddress((void**)&hlo,  g_hlo);
    cudaGetSymbolAddress((void**)&wthi, g_wthi);
    cudaGetSymbolAddress((void**)&wtlo, g_wtlo);
    cudaGetSymbolAddress((void**)&degI, g_degI);
    cudaGetSymbolAddress((void**)&degO, g_degO);
    cudaGetSymbolAddress((void**)&offI, g_offI);
    cudaGetSymbolAddress((void**)&offO, g_offO);
    cudaGetSymbolAddress((void**)&curI, g_curI);
    cudaGetSymbolAddress((void**)&curO, g_curO);
    cudaGetSymbolAddress((void**)&inEid,  g_inEid);
    cudaGetSymbolAddress((void**)&inSrc,  g_inSrc);
    cudaGetSymbolAddress((void**)&outEid, g_outEid);
    cudaGetSymbolAddress((void**)&outDst, g_outDst);

    cudaFuncSetAttribute((const void*)gemm_edge,
                         cudaFuncAttributeMaxDynamicSharedMemorySize, GEMM_SMEM);
    cudaFuncSetAttribute((const void*)gemm_mma_multi2,
                         cudaFuncAttributeMaxDynamicSharedMemorySize, GEMM_SMEM);
    cudaFuncSetAttribute((const void*)gemm_mma_multi3,
                         cudaFuncAttributeMaxDynamicSharedMemorySize, GEMM_SMEM);

    const size_t WM = (size_t)FF * FF;

    // side stream + events for capture-legal fork/join overlap
    cudaStream_t side;
    cudaStreamCreateWithFlags(&side, cudaStreamNonBlocking);
    cudaEvent_t evF, evJ, evM, evB;
    cudaEventCreateWithFlags(&evF, cudaEventDisableTiming);
    cudaEventCreateWithFlags(&evJ, cudaEventDisableTiming);
    cudaEventCreateWithFlags(&evM, cudaEventDisableTiming);
    cudaEventCreateWithFlags(&evB, cudaEventDisableTiming);

    // ---- prep: fork the big e-split onto the side stream ----
    cudaEventRecord(evF, 0);
    cudaStreamWaitEvent(side, evF, 0);
    split8<<<8192, 256, 0, side>>>(e0, ehi, elo, (size_t)EE * FF / 8);
    cudaEventRecord(evJ, side);

    prep_w_all<<<6 * 1024, 256>>>(We, Ws, Wd, Wself, Wf, Wb, wthi, wtlo);
    split8<<<4096, 256>>>(h0, hhi, hlo, (size_t)NN * FF / 8);
    fill_u<<<64, 256>>>((unsigned*)degI, NN, 0u);
    fill_u<<<64, 256>>>((unsigned*)degO, NN, 0u);
    hist_kernel<<<1024, 256>>>(src, dst, degI, degO);
    scan_kernel<<<1, 1024>>>(degI, degO, offI, offO, curI, curO);
    scatter_kernel<<<1024, 256>>>(src, dst, curI, curO, inEid, inSrc, outEid, outDst);

    dim3 gEdge(2, EE / 128);           // (2, 6250)
    dim3 gM2(4, (NN + 127) / 128);     // 2 types x 2 col blocks
    dim3 gM3(6, (NN + 127) / 128);     // 3 types x 2 col blocks

    for (int l = 0; l < LL; l++) {
        const float* hcur = l ? outh : h0;
        size_t wo = (size_t)l * WM;
        float* stEp = stE + (size_t)(l & 1) * 2 * FF;   // parity buffer

        init_layer<<<2048, 256>>>(logf, logb, stEp, stH);

        // critical-path node GEMM: Ws, Wd only (edge epilogue consumes these)
        gemm_mma_multi2<<<gM2, 256, GEMM_SMEM>>>(hhi, hlo,
            wthi + 1 * LL * WM + wo, wtlo + 1 * LL * WM + wo, hWs, hWd);

        // fork: Wself/Wf/Wb GEMM on side stream, overlaps gemm_edge
        cudaEventRecord(evF, 0);
        cudaStreamWaitEvent(side, evF, 0);
        gemm_mma_multi3<<<gM3, 256, GEMM_SMEM, side>>>(hhi, hlo,
            wthi + 3 * LL * WM + wo, wtlo + 3 * LL * WM + wo, htmp, hWf, hWb);
        cudaEventRecord(evM, side);

        // join previous side-stream edgeB (ehi/elo ready; etmp free to overwrite)
        cudaStreamWaitEvent(0, evJ, 0);

        // edge GEMM with fused edgeA epilogue
        gemm_edge<<<gEdge, 256, GEMM_SMEM>>>(ehi, elo,
            wthi + 0 * LL * WM + wo, wtlo + 0 * LL * WM + wo, etmp,
            src, dst, hWs, hWd,
            att_f + (size_t)l * FF, att_b + (size_t)l * FF,
            logf, logb, stEp);

        int wsplit = (l < LL - 1) ? 1 : 0;
        int finalL = (l == LL - 1) ? 1 : 0;

        bnfin_kernel<<<1, FF>>>(stEp, 1.f / EE);

        // fork edgeB onto side stream (after bnfinE): overlaps node chain
        cudaEventRecord(evB, 0);
        cudaStreamWaitEvent(side, evB, 0);
        edgeB_kernel<<<(int)(((size_t)EE * FF / 8 + 255) / 256), 256, 0, side>>>(
            etmp, ehi, elo, oute, stEp,
            g_e + (size_t)l * FF, b_e + (size_t)l * FF, finalL);
        cudaEventRecord(evJ, side);

        // join multi3 (htmp/hWf/hWb ready) before nodeMerge
        cudaStreamWaitEvent(0, evM, 0);

        nodeMerge_kernel<<<768, 256>>>(htmp, hWf, hWb, logf, logb,
                                       offI, inEid, inSrc, offO, outEid, outDst, stH);
        bnfin_kernel<<<1, FF>>>(stH, 1.f / NN);
        nodeB_kernel<<<(NN * FF / 8 + 255) / 256, 256>>>(
            htmp, hcur, outh, stH, g_h + (size_t)l * FF, b_h + (size_t)l * FF,
            hhi, hlo, wsplit);
    }

    // final join: last edgeB (writes d_out's e section) must complete
    cudaStreamWaitEvent(0, evJ, 0);

    cudaEventDestroy(evF);
    cudaEventDestroy(evJ);
    cudaEventDestroy(evM);
    cudaEventDestroy(evB);
    cudaStreamDestroy(side);
}

// round 16
// speedup vs baseline: 1.1097x; 1.1097x over previous
#include <cuda_runtime.h>
#include <cuda_fp16.h>
#include <math.h>
#include <stdint.h>

#define NN 50000
#define EE 800000
#define FF 256
#define LL 4
#define NEG_SLOPE 0.2f
#define BNEPS 1e-5f

// ---------------- scratch (static device globals: no runtime allocation) ----
__device__ float g_etmp[(size_t)EE * FF];   // v = e@We + hWs[src] + hWd[dst]
__device__ float g_hWs[(size_t)NN * FF];
__device__ float g_hWd[(size_t)NN * FF];
__device__ float g_hWf[(size_t)NN * FF];
__device__ float g_hWb[(size_t)NN * FF];
__device__ float g_htmp[(size_t)NN * FF];
__device__ float g_logf[EE];
__device__ float g_logb[EE];
__device__ float g_statsE[2][2 * FF];       // double-buffered by layer parity
__device__ float g_statsH[2 * FF];
// fp16 hi/lo split state (e lives ONLY here between layers)
__device__ __half g_ehi[(size_t)EE * FF];
__device__ __half g_elo[(size_t)EE * FF];
__device__ __half g_hhi[(size_t)NN * FF];
__device__ __half g_hlo[(size_t)NN * FF];
// transposed fp16 weights (single precision term): [6 types][LL][256n][256k]
__device__ __half g_wth[(size_t)6 * LL * FF * FF];
// CSR (built once per launch; graph static across layers)
__device__ int g_degI[NN];
__device__ int g_degO[NN];
__device__ int g_offI[NN + 1];
__device__ int g_offO[NN + 1];
__device__ int g_curI[NN];
__device__ int g_curO[NN];
__device__ int g_inEid[EE];
__device__ int g_inSrc[EE];
__device__ int g_outEid[EE];
__device__ int g_outDst[EE];

// ---------------- small helpers -------------------------------------------
__device__ __forceinline__ void ld8(const float* p, float* v) {
    float4 a = *(const float4*)p;
    float4 b = *(const float4*)(p + 4);
    v[0] = a.x; v[1] = a.y; v[2] = a.z; v[3] = a.w;
    v[4] = b.x; v[5] = b.y; v[6] = b.z; v[7] = b.w;
}
__device__ __forceinline__ void st8(float* p, const float* v) {
    *(float4*)p       = make_float4(v[0], v[1], v[2], v[3]);
    *(float4*)(p + 4) = make_float4(v[4], v[5], v[6], v[7]);
}
// split 8 fp32 -> packed fp16 hi / lo uint4s
__device__ __forceinline__ void split_pack(const float* v, uint4* ph, uint4* pl) {
    unsigned hw[4], lw[4];
#pragma unroll
    for (int j = 0; j < 4; j++) {
        __half h0 = __float2half_rn(v[2 * j]);
        __half h1 = __float2half_rn(v[2 * j + 1]);
        __half l0 = __float2half_rn(v[2 * j]     - __half2float(h0));
        __half l1 = __float2half_rn(v[2 * j + 1] - __half2float(h1));
        hw[j] = (unsigned)__half_as_ushort(h0) | ((unsigned)__half_as_ushort(h1) << 16);
        lw[j] = (unsigned)__half_as_ushort(l0) | ((unsigned)__half_as_ushort(l1) << 16);
    }
    *ph = make_uint4(hw[0], hw[1], hw[2], hw[3]);
    *pl = make_uint4(lw[0], lw[1], lw[2], lw[3]);
}
__device__ __forceinline__ void unpack8(uint4 uh, uint4 ul, float* e) {
    unsigned hw[4] = {uh.x, uh.y, uh.z, uh.w};
    unsigned lw[4] = {ul.x, ul.y, ul.z, ul.w};
#pragma unroll
    for (int j = 0; j < 4; j++) {
        __half2 h2 = *reinterpret_cast<__half2*>(&hw[j]);
        __half2 l2 = *reinterpret_cast<__half2*>(&lw[j]);
        e[2 * j]     = __half2float(h2.x) + __half2float(l2.x);
        e[2 * j + 1] = __half2float(h2.y) + __half2float(l2.y);
    }
}

__global__ void fill_u(unsigned* p, size_t n, unsigned v) {
    for (size_t i = (size_t)blockIdx.x * blockDim.x + threadIdx.x; i < n;
         i += (size_t)gridDim.x * blockDim.x) p[i] = v;
}
// per-layer init: logf/logb = 0, stats(parity) = 0
__global__ void init_layer(float* logf, float* logb, float* stE, float* stH) {
    for (size_t i = (size_t)blockIdx.x * blockDim.x + threadIdx.x; i < EE;
         i += (size_t)gridDim.x * blockDim.x) {
        logf[i] = 0.f; logb[i] = 0.f;
        if (i < 2 * FF) { stE[i] = 0.f; stH[i] = 0.f; }
    }
}

// ---------------- CSR build -------------------------------------------------
__global__ void hist_kernel(const int* __restrict__ src, const int* __restrict__ dst,
                            int* dI, int* dO) {
    for (int e = blockIdx.x * blockDim.x + threadIdx.x; e < EE;
         e += gridDim.x * blockDim.x) {
        atomicAdd(&dI[dst[e]], 1);
        atomicAdd(&dO[src[e]], 1);
    }
}
__global__ void scan_kernel(const int* __restrict__ dI, const int* __restrict__ dO,
                            int* offI, int* offO, int* curI, int* curO) {
    __shared__ int bufI[1024], bufO[1024];
    __shared__ int carryI, carryO;
    int tid = threadIdx.x;
    if (tid == 0) { carryI = 0; carryO = 0; }
    __syncthreads();
    for (int base = 0; base < NN; base += 1024) {
        int i = base + tid;
        int vI = (i < NN) ? dI[i] : 0;
        int vO = (i < NN) ? dO[i] : 0;
        bufI[tid] = vI; bufO[tid] = vO;
        __syncthreads();
        for (int off = 1; off < 1024; off <<= 1) {
            int aI = (tid >= off) ? bufI[tid - off] : 0;
            int aO = (tid >= off) ? bufO[tid - off] : 0;
            __syncthreads();
            bufI[tid] += aI; bufO[tid] += aO;
            __syncthreads();
        }
        if (i < NN) {
            int exI = carryI + bufI[tid] - vI;
            int exO = carryO + bufO[tid] - vO;
            offI[i] = exI; offO[i] = exO;
            curI[i] = exI; curO[i] = exO;
        }
        __syncthreads();
        if (tid == 1023) { carryI += bufI[1023]; carryO += bufO[1023]; }
        __syncthreads();
    }
    if (tid == 0) { offI[NN] = carryI; offO[NN] = carryO; }
}
__global__ void scatter_kernel(const int* __restrict__ src, const int* __restrict__ dst,
                               int* curI, int* curO,
                               int* inEid, int* inSrc, int* outEid, int* outDst) {
    for (int e = blockIdx.x * blockDim.x + threadIdx.x; e < EE;
         e += gridDim.x * blockDim.x) {
        int s = src[e], d = dst[e];
        int p = atomicAdd(&curI[d], 1);
        inEid[p] = e; inSrc[p] = s;
        int q = atomicAdd(&curO[s], 1);
        outEid[q] = e; outDst[q] = d;
    }
}

// ---------------- mma.sync primitives --------------------------------------
__device__ __forceinline__ uint32_t s2u(const void* p) {
    uint32_t a;
    asm("{ .reg .u64 t; cvta.to.shared.u64 t, %1; cvt.u32.u64 %0, t; }"
        : "=r"(a) : "l"(p));
    return a;
}
__device__ __forceinline__ void cpa16(uint32_t s, const void* g) {
    asm volatile("cp.async.cg.shared.global [%0], [%1], 16;"
                 :: "r"(s), "l"(g) : "memory");
}
__device__ __forceinline__ void cp_commit() {
    asm volatile("cp.async.commit_group;" ::: "memory");
}
template <int N>
__device__ __forceinline__ void cp_wait() {
    asm volatile("cp.async.wait_group %0;" :: "n"(N) : "memory");
}
__device__ __forceinline__ void ldm4(uint32_t* r, uint32_t a) {
    asm volatile("ldmatrix.sync.aligned.m8n8.x4.shared.b16 {%0,%1,%2,%3}, [%4];"
                 : "=r"(r[0]), "=r"(r[1]), "=r"(r[2]), "=r"(r[3]) : "r"(a));
}
__device__ __forceinline__ void mma16816h(float* d, const uint32_t* a, const uint32_t* b) {
    asm volatile(
        "mma.sync.aligned.m16n8k16.row.col.f32.f16.f16.f32 "
        "{%0,%1,%2,%3}, {%4,%5,%6,%7}, {%8,%9}, {%0,%1,%2,%3};"
        : "+f"(d[0]), "+f"(d[1]), "+f"(d[2]), "+f"(d[3])
        : "r"(a[0]), "r"(a[1]), "r"(a[2]), "r"(a[3]), "r"(b[0]), "r"(b[1]));
}

// ---------------- tensor-core GEMM core (fp16, 2-term) ----------------------
// D = Ah*Bh + Al*Bh ; A = activations fp16 hi+lo, B = weights single fp16.
#define BK 32
#define ROWB 80
#define TILEB (128 * ROWB)
#define STAGEB (3 * TILEB)                   // Ah, Al, Bh
#define GEMM_SMEM (2 * STAGEB)               // 61440

template <bool EDGE>
__device__ __forceinline__ void gemm_core(
    const __half* __restrict__ Ahi, const __half* __restrict__ Alo,
    const __half* __restrict__ Bh,
    float* __restrict__ C, int M, int row0, int col0, char* sm,
    const int* __restrict__ src, const int* __restrict__ dst,
    const float* __restrict__ hWs, const float* __restrict__ hWd,
    const float* __restrict__ af, const float* __restrict__ ab,
    float* __restrict__ logf, float* __restrict__ logb,
    float* __restrict__ stats)
{
    uint32_t sb = s2u(sm);
    int tid = threadIdx.x;
    int wid = tid >> 5, lane = tid & 31;
    int wm = (wid >> 2) * 64;
    int wn = (wid & 3) * 32;

    float acc[4][4][4];
#pragma unroll
    for (int i = 0; i < 4; i++)
#pragma unroll
        for (int j = 0; j < 4; j++)
#pragma unroll
            for (int q = 0; q < 4; q++) acc[i][j][q] = 0.f;

    int c0 = tid, c1 = tid + 256;
    int r0c = c0 >> 2, cc0 = c0 & 3;
    int r1c = c1 >> 2, cc1 = c1 & 3;
    int ga0 = min(row0 + r0c, M - 1);
    int ga1 = min(row0 + r1c, M - 1);
    int gb0 = col0 + r0c;
    int gb1 = col0 + r1c;
    uint32_t so0 = (uint32_t)(r0c * ROWB + cc0 * 16);
    uint32_t so1 = (uint32_t)(r1c * ROWB + cc1 * 16);

#define PREFETCH(ks, buf) do {                                                   \
        int k0 = (ks) * BK;                                                      \
        uint32_t s0 = sb + (buf) * STAGEB + so0;                                 \
        uint32_t s1 = sb + (buf) * STAGEB + so1;                                 \
        cpa16(s0,              Ahi + (size_t)ga0 * FF + k0 + cc0 * 8);           \
        cpa16(s0 + TILEB,      Alo + (size_t)ga0 * FF + k0 + cc0 * 8);           \
        cpa16(s0 + 2 * TILEB,  Bh  + (size_t)gb0 * FF + k0 + cc0 * 8);           \
        cpa16(s1,              Ahi + (size_t)ga1 * FF + k0 + cc1 * 8);           \
        cpa16(s1 + TILEB,      Alo + (size_t)ga1 * FF + k0 + cc1 * 8);           \
        cpa16(s1 + 2 * TILEB,  Bh  + (size_t)gb1 * FF + k0 + cc1 * 8);           \
        cp_commit();                                                             \
    } while (0)

    int a_row  = wm + (lane & 15);
    int a_cch  = (lane >> 4) & 1;
    int b_row  = wn + (lane & 7) + ((lane >> 4) & 1) * 8;
    int b_cch  = ((lane >> 3) & 1) * 8;

    PREFETCH(0, 0);

    for (int ks = 0; ks < FF / BK; ks++) {
        int buf = ks & 1;
        if (ks < FF / BK - 1) { PREFETCH(ks + 1, buf ^ 1); cp_wait<1>(); }
        else                  { cp_wait<0>(); }
        __syncthreads();

        uint32_t base = sb + buf * STAGEB;
#pragma unroll
        for (int kc = 0; kc < 2; kc++) {
            int klocal = kc * 16;
            uint32_t ah[4][4], al[4][4];
#pragma unroll
            for (int i = 0; i < 4; i++) {
                uint32_t ad = base + (uint32_t)((a_row + i * 16) * ROWB
                                                + (klocal + a_cch * 8) * 2);
                ldm4(ah[i], ad);
                ldm4(al[i], ad + TILEB);
            }
            uint32_t bh[2][4];
#pragma unroll
            for (int jj = 0; jj < 2; jj++) {
                uint32_t bd = base + 2 * TILEB
                            + (uint32_t)((b_row + jj * 16) * ROWB
                                         + (klocal + b_cch) * 2);
                ldm4(bh[jj], bd);
            }
            // term 1: Ah * Bh (16 independent accumulators)
#pragma unroll
            for (int i = 0; i < 4; i++)
#pragma unroll
                for (int j = 0; j < 4; j++)
                    mma16816h(acc[i][j], ah[i], &bh[j >> 1][(j & 1) * 2]);
            // term 2: Al * Bh
#pragma unroll
            for (int i = 0; i < 4; i++)
#pragma unroll
                for (int j = 0; j < 4; j++)
                    mma16816h(acc[i][j], al[i], &bh[j >> 1][(j & 1) * 2]);
        }
        __syncthreads();
    }

    if (!EDGE) {
#pragma unroll
        for (int i = 0; i < 4; i++) {
            int r = row0 + wm + i * 16 + (lane >> 2);
            int cbase = col0 + wn + (lane & 3) * 2;
            if (r < M) {
                float* cp = C + (size_t)r * FF + cbase;
#pragma unroll
                for (int j = 0; j < 4; j++)
                    *(float2*)(cp + j * 8) = make_float2(acc[i][j][0], acc[i][j][1]);
            }
            if (r + 8 < M) {
                float* cp = C + (size_t)(r + 8) * FF + cbase;
#pragma unroll
                for (int j = 0; j < 4; j++)
                    *(float2*)(cp + j * 8) = make_float2(acc[i][j][2], acc[i][j][3]);
            }
        }
    } else {
        float s8[8], q8[8];
#pragma unroll
        for (int k = 0; k < 8; k++) { s8[k] = 0.f; q8[k] = 0.f; }
        int cbase = col0 + wn + (lane & 3) * 2;
#pragma unroll
        for (int i = 0; i < 4; i++) {
            int r  = row0 + wm + i * 16 + (lane >> 2);
            int r2 = r + 8;
            int sA = src[r],  dA = dst[r];
            int sB = src[r2], dB = dst[r2];
            float lf1 = 0.f, lb1 = 0.f, lf2 = 0.f, lb2 = 0.f;
#pragma unroll
            for (int j = 0; j < 4; j++) {
                int c = cbase + j * 8;
                float2 afv = *(const float2*)(af + c);
                float2 abv = *(const float2*)(ab + c);
                float2 xs = *(const float2*)(hWs + (size_t)sA * FF + c);
                float2 yd = *(const float2*)(hWd + (size_t)dA * FF + c);
                float v0 = acc[i][j][0] + xs.x + yd.x;
                float v1 = acc[i][j][1] + xs.y + yd.y;
                *(float2*)(C + (size_t)r * FF + c) = make_float2(v0, v1);
                lf1 += v0 * afv.x + v1 * afv.y;
                lb1 += v0 * abv.x + v1 * abv.y;
                s8[2 * j] += v0;       s8[2 * j + 1] += v1;
                q8[2 * j] += v0 * v0;  q8[2 * j + 1] += v1 * v1;
                float2 xs2 = *(const float2*)(hWs + (size_t)sB * FF + c);
                float2 yd2 = *(const float2*)(hWd + (size_t)dB * FF + c);
                float w0 = acc[i][j][2] + xs2.x + yd2.x;
                float w1 = acc[i][j][3] + xs2.y + yd2.y;
                *(float2*)(C + (size_t)r2 * FF + c) = make_float2(w0, w1);
                lf2 += w0 * afv.x + w1 * afv.y;
                lb2 += w0 * abv.x + w1 * abv.y;
                s8[2 * j] += w0;       s8[2 * j + 1] += w1;
                q8[2 * j] += w0 * w0;  q8[2 * j + 1] += w1 * w1;
            }
#pragma unroll
            for (int o = 1; o <= 2; o <<= 1) {
                lf1 += __shfl_xor_sync(0xffffffffu, lf1, o);
                lb1 += __shfl_xor_sync(0xffffffffu, lb1, o);
                lf2 += __shfl_xor_sync(0xffffffffu, lf2, o);
                lb2 += __shfl_xor_sync(0xffffffffu, lb2, o);
            }
            if ((lane & 3) == 0) {
                atomicAdd(&logf[r],  lf1);
                atomicAdd(&logb[r],  lb1);
                atomicAdd(&logf[r2], lf2);
                atomicAdd(&logb[r2], lb2);
            }
        }
#pragma unroll
        for (int k = 0; k < 8; k++) {
#pragma unroll
            for (int o = 4; o <= 16; o <<= 1) {
                s8[k] += __shfl_xor_sync(0xffffffffu, s8[k], o);
                q8[k] += __shfl_xor_sync(0xffffffffu, q8[k], o);
            }
        }
        if (lane < 4) {
            int cb = col0 + wn + lane * 2;
#pragma unroll
            for (int j = 0; j < 4; j++) {
                atomicAdd(&stats[cb + j * 8],          s8[2 * j]);
                atomicAdd(&stats[cb + j * 8 + 1],      s8[2 * j + 1]);
                atomicAdd(&stats[FF + cb + j * 8],     q8[2 * j]);
                atomicAdd(&stats[FF + cb + j * 8 + 1], q8[2 * j + 1]);
            }
        }
    }
#undef PREFETCH
}

__global__ void __launch_bounds__(256, 1)
gemm_edge(const __half* __restrict__ Ahi, const __half* __restrict__ Alo,
          const __half* __restrict__ Bh,
          float* __restrict__ C,
          const int* __restrict__ src, const int* __restrict__ dst,
          const float* __restrict__ hWs, const float* __restrict__ hWd,
          const float* __restrict__ af, const float* __restrict__ ab,
          float* __restrict__ logf, float* __restrict__ logb,
          float* __restrict__ stats)
{
    extern __shared__ __align__(128) char sm[];
    gemm_core<true>(Ahi, Alo, Bh, C, EE, blockIdx.y * 128, blockIdx.x * 128,
                    sm, src, dst, hWs, hWd, af, ab, logf, logb, stats);
}

// node GEMM, 2 types (Ws, Wd) — critical path
__global__ void __launch_bounds__(256, 1)
gemm_mma_multi2(const __half* __restrict__ Ahi, const __half* __restrict__ Alo,
                const __half* __restrict__ Bh0, float* C0, float* C1)
{
    extern __shared__ __align__(128) char sm[];
    int t = blockIdx.x >> 1;
    int col0 = (blockIdx.x & 1) * 128;
    size_t ws = (size_t)t * LL * FF * FF;
    float* C = (t == 0) ? C0 : C1;
    gemm_core<false>(Ahi, Alo, Bh0 + ws, C, NN, blockIdx.y * 128, col0,
                     sm, nullptr, nullptr, nullptr, nullptr, nullptr, nullptr,
                     nullptr, nullptr, nullptr);
}

// node GEMM, 3 types (Wself, Wf, Wb) — side stream
__global__ void __launch_bounds__(256, 1)
gemm_mma_multi3(const __half* __restrict__ Ahi, const __half* __restrict__ Alo,
                const __half* __restrict__ Bh0, float* C0, float* C1, float* C2)
{
    extern __shared__ __align__(128) char sm[];
    int t = blockIdx.x >> 1;
    int col0 = (blockIdx.x & 1) * 128;
    size_t ws = (size_t)t * LL * FF * FF;
    float* C = (t == 0) ? C0 : (t == 1) ? C1 : C2;
    gemm_core<false>(Ahi, Alo, Bh0 + ws, C, NN, blockIdx.y * 128, col0,
                     sm, nullptr, nullptr, nullptr, nullptr, nullptr, nullptr,
                     nullptr, nullptr, nullptr);
}

// ---------------- weight transpose + fp16 convert (all 6 types, one launch) -
__global__ void prep_w_all(const float* W0, const float* W1, const float* W2,
                           const float* W3, const float* W4, const float* W5,
                           __half* __restrict__ wh)
{
    int t   = blockIdx.x >> 10;
    int bl  = blockIdx.x & 1023;
    int l   = bl >> 8;
    int i   = (bl & 255) * 256 + threadIdx.x;
    int n = i >> 8, k = i & 255;
    const float* W = (t == 0) ? W0 : (t == 1) ? W1 : (t == 2) ? W2
                   : (t == 3) ? W3 : (t == 4) ? W4 : W5;
    size_t off = ((size_t)t * LL + l) * FF * FF;
    wh[off + i] = __float2half_rn(W[(size_t)l * FF * FF + (size_t)k * FF + n]);
}

// ---------------- fp32 -> fp16 hi/lo split (bulk) --------------------------
__global__ void split8(const float* __restrict__ x,
                       __half* __restrict__ hi, __half* __restrict__ lo,
                       size_t n8)
{
    for (size_t i = (size_t)blockIdx.x * blockDim.x + threadIdx.x; i < n8;
         i += (size_t)gridDim.x * blockDim.x) {
        float v[8];
        ld8(x + i * 8, v);
        uint4 uh, ul;
        split_pack(v, &uh, &ul);
        *(uint4*)(hi + i * 8) = uh;
        *(uint4*)(lo + i * 8) = ul;
    }
}

// ---------------- BN finalize ----------------------------------------------
__global__ void bnfin_kernel(float* stats, float inv_cnt) {
    int f = threadIdx.x;
    float mu  = stats[f] * inv_cnt;
    float var = stats[FF + f] * inv_cnt - mu * mu;
    stats[f]      = mu;
    stats[FF + f] = rsqrtf(var + BNEPS);
}

// ---------------- edge pass B: pure streaming -------------------------------
__global__ void __launch_bounds__(256)
edgeB_kernel(const float* __restrict__ etmp,
             __half* __restrict__ ehi, __half* __restrict__ elo,
             float* __restrict__ e_out,
             const float* __restrict__ stats,
             const float* __restrict__ ge, const float* __restrict__ be,
             int finalL)
{
    size_t i = (size_t)blockIdx.x * blockDim.x + threadIdx.x;
    const size_t NV = (size_t)EE * FF / 8;
    if (i >= NV) return;
    int c = ((int)i & 31) * 8;
    float t[8], ein[8], o[8];
    ld8(etmp + i * 8, t);
    uint4 uh = *(const uint4*)(ehi + i * 8);
    uint4 ul = *(const uint4*)(elo + i * 8);
    unpack8(uh, ul, ein);
#pragma unroll
    for (int j = 0; j < 8; j++) {
        float bn = (t[j] - stats[c + j]) * stats[FF + c + j] * ge[c + j] + be[c + j];
        o[j] = ein[j] + (bn > 0.f ? bn : 0.f);
    }
    if (finalL) {
        st8(e_out + i * 8, o);
    } else {
        uint4 nh, nl;
        split_pack(o, &nh, &nl);
        *(uint4*)(ehi + i * 8) = nh;
        *(uint4*)(elo + i * 8) = nl;
    }
}

// ---------------- node merge: local segment-max + gather aggregation --------
__global__ void __launch_bounds__(256)
nodeMerge_kernel(float* __restrict__ htmp,
                 const float* __restrict__ hWf, const float* __restrict__ hWb,
                 const float* __restrict__ logf, const float* __restrict__ logb,
                 const int* __restrict__ offI, const int* __restrict__ inEid,
                 const int* __restrict__ inSrc,
                 const int* __restrict__ offO, const int* __restrict__ outEid,
                 const int* __restrict__ outDst,
                 float* __restrict__ stats)
{
    int lane = threadIdx.x & 31;
    int gw = (blockIdx.x * blockDim.x + threadIdx.x) >> 5;
    int nw = (gridDim.x * blockDim.x) >> 5;
    int fb = lane * 8;

    float s[8], sq[8];
#pragma unroll
    for (int j = 0; j < 8; j++) { s[j] = 0.f; sq[j] = 0.f; }

    for (int n = gw; n < NN; n += nw) {
        float accf[8];
#pragma unroll
        for (int j = 0; j < 8; j++) accf[j] = 0.f;
        float denf = 0.f;
        {
            int b0 = offI[n], b1 = offI[n + 1];
            float mn = -1e30f;
            for (int k = b0 + lane; k < b1; k += 32) {
                float r = logf[inEid[k]];
                r = r > 0.f ? r : NEG_SLOPE * r;
                mn = fmaxf(mn, r);
            }
#pragma unroll
            for (int o = 16; o > 0; o >>= 1)
                mn = fmaxf(mn, __shfl_xor_sync(0xffffffffu, mn, o));
            for (int cb = b0; cb < b1; cb += 32) {
                int cnt = min(32, b1 - cb);
                float ex = 0.f; int si = 0;
                if (lane < cnt) {
                    int k = cb + lane;
                    si = inSrc[k];
                    float r = logf[inEid[k]];
                    r = r > 0.f ? r : NEG_SLOPE * r;
                    ex = expf(r - mn);
                }
                for (int j = 0; j < cnt; j++) {
                    float e  = __shfl_sync(0xffffffffu, ex, j);
                    int   s_ = __shfl_sync(0xffffffffu, si, j);
                    float w[8];
                    ld8(hWf + (size_t)s_ * FF + fb, w);
                    denf += e;
#pragma unroll
                    for (int q = 0; q < 8; q++) accf[q] += e * w[q];
                }
            }
        }
        float accb[8];
#pragma unroll
        for (int j = 0; j < 8; j++) accb[j] = 0.f;
        float denb = 0.f;
        {
            int b0 = offO[n], b1 = offO[n + 1];
            float mn = -1e30f;
            for (int k = b0 + lane; k < b1; k += 32) {
                float r = logb[outEid[k]];
                r = r > 0.f ? r : NEG_SLOPE * r;
                mn = fmaxf(mn, r);
            }
#pragma unroll
            for (int o = 16; o > 0; o >>= 1)
                mn = fmaxf(mn, __shfl_xor_sync(0xffffffffu, mn, o));
            for (int cb = b0; cb < b1; cb += 32) {
                int cnt = min(32, b1 - cb);
                float ex = 0.f; int di = 0;
                if (lane < cnt) {
                    int k = cb + lane;
                    di = outDst[k];
                    float r = logb[outEid[k]];
                    r = r > 0.f ? r : NEG_SLOPE * r;
                    ex = expf(r - mn);
                }
                for (int j = 0; j < cnt; j++) {
                    float e  = __shfl_sync(0xffffffffu, ex, j);
                    int   d_ = __shfl_sync(0xffffffffu, di, j);
                    float w[8];
                    ld8(hWb + (size_t)d_ * FF + fb, w);
                    denb += e;
#pragma unroll
                    for (int q = 0; q < 8; q++) accb[q] += e * w[q];
                }
            }
        }
        float rf = 1.f / (denf + 1e-9f);
        float rb = 1.f / (denb + 1e-9f);
        float v[8];
        float* ph = htmp + (size_t)n * FF + fb;
        ld8(ph, v);
#pragma unroll
        for (int j = 0; j < 8; j++) {
            v[j] = v[j] + accf[j] * rf + accb[j] * rb;
            s[j]  += v[j];
            sq[j] += v[j] * v[j];
        }
        st8(ph, v);
    }
#pragma unroll
    for (int j = 0; j < 8; j++) {
        atomicAdd(&stats[fb + j], s[j]);
        atomicAdd(&stats[FF + fb + j], sq[j]);
    }
}

// ---------------- node pass B ----------------------------------------------
__global__ void __launch_bounds__(256)
nodeB_kernel(const float* __restrict__ htmp, const float* __restrict__ h_in,
             float* __restrict__ h_out, const float* __restrict__ stats,
             const float* __restrict__ gh, const float* __restrict__ bh,
             __half* __restrict__ hhi, __half* __restrict__ hlo,
             int wsplit)
{
    int i = blockIdx.x * blockDim.x + threadIdx.x;
    const int NV = NN * FF / 8;
    if (i >= NV) return;
    int c = (i & 31) * 8;
    float t[8], hv[8], o[8];
    ld8(htmp + (size_t)i * 8, t);
    ld8(h_in + (size_t)i * 8, hv);
#pragma unroll
    for (int j = 0; j < 8; j++) {
        float bn = (t[j] - stats[c + j]) * stats[FF + c + j] * gh[c + j] + bh[c + j];
        o[j] = hv[j] + (bn > 0.f ? bn : 0.f);
    }
    st8(h_out + (size_t)i * 8, o);
    if (wsplit) {
        uint4 uh, ul;
        split_pack(o, &uh, &ul);
        *(uint4*)(hhi + (size_t)i * 8) = uh;
        *(uint4*)(hlo + (size_t)i * 8) = ul;
    }
}

// ---------------- launch ---------------------------------------------------
extern "C" void kernel_launch(void* const* d_in, const int* in_sizes, int n_in,
                              void* d_out, int out_size)
{
    (void)in_sizes; (void)n_in; (void)out_size;
    const float* h0    = (const float*)d_in[0];
    const float* e0    = (const float*)d_in[1];
    const int*   src   = (const int*)d_in[2];
    const int*   dst   = (const int*)d_in[3];
    const float* We    = (const float*)d_in[4];
    const float* Ws    = (const float*)d_in[5];
    const float* Wd    = (const float*)d_in[6];
    const float* Wself = (const float*)d_in[7];
    const float* Wf    = (const float*)d_in[8];
    const float* Wb    = (const float*)d_in[9];
    const float* att_f = (const float*)d_in[10];
    const float* att_b = (const float*)d_in[11];
    const float* g_e   = (const float*)d_in[12];
    const float* b_e   = (const float*)d_in[13];
    const float* g_h   = (const float*)d_in[14];
    const float* b_h   = (const float*)d_in[15];

    float* outh = (float*)d_out;
    float* oute = outh + (size_t)NN * FF;

    float *etmp, *hWs, *hWd, *hWf, *hWb, *htmp;
    float *logf, *logb, *stE, *stH;
    __half *ehi, *elo, *hhi, *hlo, *wth;
    int *degI, *degO, *offI, *offO, *curI, *curO, *inEid, *inSrc, *outEid, *outDst;
    cudaGetSymbolAddress((void**)&etmp, g_etmp);
    cudaGetSymbolAddress((void**)&hWs,  g_hWs);
    cudaGetSymbolAddress((void**)&hWd,  g_hWd);
    cudaGetSymbolAddress((void**)&hWf,  g_hWf);
    cudaGetSymbolAddress((void**)&hWb,  g_hWb);
    cudaGetSymbolAddress((void**)&htmp, g_htmp);
    cudaGetSymbolAddress((void**)&logf, g_logf);
    cudaGetSymbolAddress((void**)&logb, g_logb);
    cudaGetSymbolAddress((void**)&stE,  g_statsE);
    cudaGetSymbolAddress((void**)&stH,  g_statsH);
    cudaGetSymbolAddress((void**)&ehi,  g_ehi);
    cudaGetSymbolAddress((void**)&elo,  g_elo);
    cudaGetSymbolAddress((void**)&hhi,  g_hhi);
    cudaGetSymbolAddress((void**)&hlo,  g_hlo);
    cudaGetSymbolAddress((void**)&wth,  g_wth);
    cudaGetSymbolAddress((void**)&degI, g_degI);
    cudaGetSymbolAddress((void**)&degO, g_degO);
    cudaGetSymbolAddress((void**)&offI, g_offI);
    cudaGetSymbolAddress((void**)&offO, g_offO);
    cudaGetSymbolAddress((void**)&curI, g_curI);
    cudaGetSymbolAddress((void**)&curO, g_curO);
    cudaGetSymbolAddress((void**)&inEid,  g_inEid);
    cudaGetSymbolAddress((void**)&inSrc,  g_inSrc);
    cudaGetSymbolAddress((void**)&outEid, g_outEid);
    cudaGetSymbolAddress((void**)&outDst, g_outDst);

    cudaFuncSetAttribute((const void*)gemm_edge,
                         cudaFuncAttributeMaxDynamicSharedMemorySize, GEMM_SMEM);
    cudaFuncSetAttribute((const void*)gemm_mma_multi2,
                         cudaFuncAttributeMaxDynamicSharedMemorySize, GEMM_SMEM);
    cudaFuncSetAttribute((const void*)gemm_mma_multi3,
                         cudaFuncAttributeMaxDynamicSharedMemorySize, GEMM_SMEM);

    const size_t WM = (size_t)FF * FF;

    // side stream + events for capture-legal fork/join overlap
    cudaStream_t side;
    cudaStreamCreateWithFlags(&side, cudaStreamNonBlocking);
    cudaEvent_t evF, evJ, evM, evB;
    cudaEventCreateWithFlags(&evF, cudaEventDisableTiming);
    cudaEventCreateWithFlags(&evJ, cudaEventDisableTiming);
    cudaEventCreateWithFlags(&evM, cudaEventDisableTiming);
    cudaEventCreateWithFlags(&evB, cudaEventDisableTiming);

    // ---- prep: fork the big e-split onto the side stream ----
    cudaEventRecord(evF, 0);
    cudaStreamWaitEvent(side, evF, 0);
    split8<<<8192, 256, 0, side>>>(e0, ehi, elo, (size_t)EE * FF / 8);
    cudaEventRecord(evJ, side);

    prep_w_all<<<6 * 1024, 256>>>(We, Ws, Wd, Wself, Wf, Wb, wth);
    split8<<<4096, 256>>>(h0, hhi, hlo, (size_t)NN * FF / 8);
    fill_u<<<64, 256>>>((unsigned*)degI, NN, 0u);
    fill_u<<<64, 256>>>((unsigned*)degO, NN, 0u);
    hist_kernel<<<1024, 256>>>(src, dst, degI, degO);
    scan_kernel<<<1, 1024>>>(degI, degO, offI, offO, curI, curO);
    scatter_kernel<<<1024, 256>>>(src, dst, curI, curO, inEid, inSrc, outEid, outDst);

    dim3 gEdge(2, EE / 128);           // (2, 6250)
    dim3 gM2(4, (NN + 127) / 128);     // 2 types x 2 col blocks
    dim3 gM3(6, (NN + 127) / 128);     // 3 types x 2 col blocks

    for (int l = 0; l < LL; l++) {
        const float* hcur = l ? outh : h0;
        size_t wo = (size_t)l * WM;
        float* stEp = stE + (size_t)(l & 1) * 2 * FF;   // parity buffer

        init_layer<<<2048, 256>>>(logf, logb, stEp, stH);

        // critical-path node GEMM: Ws, Wd only (edge epilogue consumes these)
        gemm_mma_multi2<<<gM2, 256, GEMM_SMEM>>>(hhi, hlo,
            wth + 1 * LL * WM + wo, hWs, hWd);

        // fork: Wself/Wf/Wb GEMM on side stream
        cudaEventRecord(evF, 0);
        cudaStreamWaitEvent(side, evF, 0);
        gemm_mma_multi3<<<gM3, 256, GEMM_SMEM, side>>>(hhi, hlo,
            wth + 3 * LL * WM + wo, htmp, hWf, hWb);
        cudaEventRecord(evM, side);

        // join previous side-stream edgeB (ehi/elo ready; etmp free to overwrite)
        cudaStreamWaitEvent(0, evJ, 0);

        // edge GEMM with fused edgeA epilogue
        gemm_edge<<<gEdge, 256, GEMM_SMEM>>>(ehi, elo,
            wth + 0 * LL * WM + wo, etmp,
            src, dst, hWs, hWd,
            att_f + (size_t)l * FF, att_b + (size_t)l * FF,
            logf, logb, stEp);

        int wsplit = (l < LL - 1) ? 1 : 0;
        int finalL = (l == LL - 1) ? 1 : 0;

        bnfin_kernel<<<1, FF>>>(stEp, 1.f / EE);

        // fork edgeB onto side stream (after bnfinE): overlaps node chain
        cudaEventRecord(evB, 0);
        cudaStreamWaitEvent(side, evB, 0);
        edgeB_kernel<<<(int)(((size_t)EE * FF / 8 + 255) / 256), 256, 0, side>>>(
            etmp, ehi, elo, oute, stEp,
            g_e + (size_t)l * FF, b_e + (size_t)l * FF, finalL);
        cudaEventRecord(evJ, side);

        // join multi3 (htmp/hWf/hWb ready) before nodeMerge
        cudaStreamWaitEvent(0, evM, 0);

        nodeMerge_kernel<<<768, 256>>>(htmp, hWf, hWb, logf, logb,
                                       offI, inEid, inSrc, offO, outEid, outDst, stH);
        bnfin_kernel<<<1, FF>>>(stH, 1.f / NN);
        nodeB_kernel<<<(NN * FF / 8 + 255) / 256, 256>>>(
            htmp, hcur, outh, stH, g_h + (size_t)l * FF, b_h + (size_t)l * FF,
            hhi, hlo, wsplit);
    }

    // final join: last edgeB (writes d_out's e section) must complete
    cudaStreamWaitEvent(0, evJ, 0);

    cudaEventDestroy(evF);
    cudaEventDestroy(evJ);
    cudaEventDestroy(evM);
    cudaEventDestroy(evB);
    cudaStreamDestroy(side);
}

// round 17
// speedup vs baseline: 1.2059x; 1.0867x over previous
#include <cuda_runtime.h>
#include <cuda_fp16.h>
#include <math.h>
#include <stdint.h>

#define NN 50000
#define EE 800000
#define FF 256
#define LL 4
#define NEG_SLOPE 0.2f
#define BNEPS 1e-5f

// ---------------- scratch (static device globals: no runtime allocation) ----
__device__ float g_etmp[(size_t)EE * FF];   // v = e@We + hWs[src] + hWd[dst]
__device__ float g_hWs[(size_t)NN * FF];
__device__ float g_hWd[(size_t)NN * FF];
__device__ float g_hWf[(size_t)NN * FF];
__device__ float g_hWb[(size_t)NN * FF];
__device__ float g_htmp[(size_t)NN * FF];
__device__ float g_logf[EE];
__device__ float g_logb[EE];
__device__ float g_statsE[2][2 * FF];       // double-buffered by layer parity
__device__ float g_statsH[2 * FF];
// fp16 hi/lo split state (e lives ONLY here between layers)
__device__ __half g_ehi[(size_t)EE * FF];
__device__ __half g_elo[(size_t)EE * FF];
__device__ __half g_hhi[(size_t)NN * FF];
__device__ __half g_hlo[(size_t)NN * FF];
// transposed fp16 weights (single precision term): [6 types][LL][256n][256k]
__device__ __half g_wth[(size_t)6 * LL * FF * FF];
// CSR (built once per launch; graph static across layers)
__device__ int g_degI[NN];
__device__ int g_degO[NN];
__device__ int g_offI[NN + 1];
__device__ int g_offO[NN + 1];
__device__ int g_curI[NN];
__device__ int g_curO[NN];
__device__ int g_inEid[EE];
__device__ int g_inSrc[EE];
__device__ int g_outEid[EE];
__device__ int g_outDst[EE];

// ---------------- small helpers -------------------------------------------
__device__ __forceinline__ void ld8(const float* p, float* v) {
    float4 a = *(const float4*)p;
    float4 b = *(const float4*)(p + 4);
    v[0] = a.x; v[1] = a.y; v[2] = a.z; v[3] = a.w;
    v[4] = b.x; v[5] = b.y; v[6] = b.z; v[7] = b.w;
}
__device__ __forceinline__ void st8(float* p, const float* v) {
    *(float4*)p       = make_float4(v[0], v[1], v[2], v[3]);
    *(float4*)(p + 4) = make_float4(v[4], v[5], v[6], v[7]);
}
// split 8 fp32 -> packed fp16 hi / lo uint4s
__device__ __forceinline__ void split_pack(const float* v, uint4* ph, uint4* pl) {
    unsigned hw[4], lw[4];
#pragma unroll
    for (int j = 0; j < 4; j++) {
        __half h0 = __float2half_rn(v[2 * j]);
        __half h1 = __float2half_rn(v[2 * j + 1]);
        __half l0 = __float2half_rn(v[2 * j]     - __half2float(h0));
        __half l1 = __float2half_rn(v[2 * j + 1] - __half2float(h1));
        hw[j] = (unsigned)__half_as_ushort(h0) | ((unsigned)__half_as_ushort(h1) << 16);
        lw[j] = (unsigned)__half_as_ushort(l0) | ((unsigned)__half_as_ushort(l1) << 16);
    }
    *ph = make_uint4(hw[0], hw[1], hw[2], hw[3]);
    *pl = make_uint4(lw[0], lw[1], lw[2], lw[3]);
}
__device__ __forceinline__ void unpack8(uint4 uh, uint4 ul, float* e) {
    unsigned hw[4] = {uh.x, uh.y, uh.z, uh.w};
    unsigned lw[4] = {ul.x, ul.y, ul.z, ul.w};
#pragma unroll
    for (int j = 0; j < 4; j++) {
        __half2 h2 = *reinterpret_cast<__half2*>(&hw[j]);
        __half2 l2 = *reinterpret_cast<__half2*>(&lw[j]);
        e[2 * j]     = __half2float(h2.x) + __half2float(l2.x);
        e[2 * j + 1] = __half2float(h2.y) + __half2float(l2.y);
    }
}

__global__ void fill_u(unsigned* p, size_t n, unsigned v) {
    for (size_t i = (size_t)blockIdx.x * blockDim.x + threadIdx.x; i < n;
         i += (size_t)gridDim.x * blockDim.x) p[i] = v;
}
// per-layer init: logf/logb = 0, stats(parity) = 0
__global__ void init_layer(float* logf, float* logb, float* stE, float* stH) {
    for (size_t i = (size_t)blockIdx.x * blockDim.x + threadIdx.x; i < EE;
         i += (size_t)gridDim.x * blockDim.x) {
        logf[i] = 0.f; logb[i] = 0.f;
        if (i < 2 * FF) { stE[i] = 0.f; stH[i] = 0.f; }
    }
}

// ---------------- CSR build -------------------------------------------------
__global__ void hist_kernel(const int* __restrict__ src, const int* __restrict__ dst,
                            int* dI, int* dO) {
    for (int e = blockIdx.x * blockDim.x + threadIdx.x; e < EE;
         e += gridDim.x * blockDim.x) {
        atomicAdd(&dI[dst[e]], 1);
        atomicAdd(&dO[src[e]], 1);
    }
}
__global__ void scan_kernel(const int* __restrict__ dI, const int* __restrict__ dO,
                            int* offI, int* offO, int* curI, int* curO) {
    __shared__ int bufI[1024], bufO[1024];
    __shared__ int carryI, carryO;
    int tid = threadIdx.x;
    if (tid == 0) { carryI = 0; carryO = 0; }
    __syncthreads();
    for (int base = 0; base < NN; base += 1024) {
        int i = base + tid;
        int vI = (i < NN) ? dI[i] : 0;
        int vO = (i < NN) ? dO[i] : 0;
        bufI[tid] = vI; bufO[tid] = vO;
        __syncthreads();
        for (int off = 1; off < 1024; off <<= 1) {
            int aI = (tid >= off) ? bufI[tid - off] : 0;
            int aO = (tid >= off) ? bufO[tid - off] : 0;
            __syncthreads();
            bufI[tid] += aI; bufO[tid] += aO;
            __syncthreads();
        }
        if (i < NN) {
            int exI = carryI + bufI[tid] - vI;
            int exO = carryO + bufO[tid] - vO;
            offI[i] = exI; offO[i] = exO;
            curI[i] = exI; curO[i] = exO;
        }
        __syncthreads();
        if (tid == 1023) { carryI += bufI[1023]; carryO += bufO[1023]; }
        __syncthreads();
    }
    if (tid == 0) { offI[NN] = carryI; offO[NN] = carryO; }
}
__global__ void scatter_kernel(const int* __restrict__ src, const int* __restrict__ dst,
                               int* curI, int* curO,
                               int* inEid, int* inSrc, int* outEid, int* outDst) {
    for (int e = blockIdx.x * blockDim.x + threadIdx.x; e < EE;
         e += gridDim.x * blockDim.x) {
        int s = src[e], d = dst[e];
        int p = atomicAdd(&curI[d], 1);
        inEid[p] = e; inSrc[p] = s;
        int q = atomicAdd(&curO[s], 1);
        outEid[q] = e; outDst[q] = d;
    }
}

// ---------------- mma.sync primitives --------------------------------------
__device__ __forceinline__ uint32_t s2u(const void* p) {
    uint32_t a;
    asm("{ .reg .u64 t; cvta.to.shared.u64 t, %1; cvt.u32.u64 %0, t; }"
        : "=r"(a) : "l"(p));
    return a;
}
__device__ __forceinline__ void cpa16(uint32_t s, const void* g) {
    asm volatile("cp.async.cg.shared.global [%0], [%1], 16;"
                 :: "r"(s), "l"(g) : "memory");
}
__device__ __forceinline__ void cp_commit() {
    asm volatile("cp.async.commit_group;" ::: "memory");
}
template <int N>
__device__ __forceinline__ void cp_wait() {
    asm volatile("cp.async.wait_group %0;" :: "n"(N) : "memory");
}
__device__ __forceinline__ void ldm4(uint32_t* r, uint32_t a) {
    asm volatile("ldmatrix.sync.aligned.m8n8.x4.shared.b16 {%0,%1,%2,%3}, [%4];"
                 : "=r"(r[0]), "=r"(r[1]), "=r"(r[2]), "=r"(r[3]) : "r"(a));
}
__device__ __forceinline__ void mma16816h(float* d, const uint32_t* a, const uint32_t* b) {
    asm volatile(
        "mma.sync.aligned.m16n8k16.row.col.f32.f16.f16.f32 "
        "{%0,%1,%2,%3}, {%4,%5,%6,%7}, {%8,%9}, {%0,%1,%2,%3};"
        : "+f"(d[0]), "+f"(d[1]), "+f"(d[2]), "+f"(d[3])
        : "r"(a[0]), "r"(a[1]), "r"(a[2]), "r"(a[3]), "r"(b[0]), "r"(b[1]));
}

// ---------------- tensor-core GEMM core (fp16, 2-term) ----------------------
// D = Ah*Bh + Al*Bh ; A = activations fp16 hi+lo, B = weights single fp16.
// 2 CTAs/SM (60KB smem each): 16 warps/SM to hide HMMA/cp.async latency.
#define BK 32
#define ROWB 80
#define TILEB (128 * ROWB)
#define STAGEB (3 * TILEB)                   // Ah, Al, Bh
#define GEMM_SMEM (2 * STAGEB)               // 61440

template <bool EDGE>
__device__ __forceinline__ void gemm_core(
    const __half* __restrict__ Ahi, const __half* __restrict__ Alo,
    const __half* __restrict__ Bh,
    float* __restrict__ C, int M, int row0, int col0, char* sm,
    const int* __restrict__ src, const int* __restrict__ dst,
    const float* __restrict__ hWs, const float* __restrict__ hWd,
    const float* __restrict__ af, const float* __restrict__ ab,
    float* __restrict__ logf, float* __restrict__ logb,
    float* __restrict__ stats)
{
    uint32_t sb = s2u(sm);
    int tid = threadIdx.x;
    int wid = tid >> 5, lane = tid & 31;
    int wm = (wid >> 2) * 64;
    int wn = (wid & 3) * 32;

    float acc[4][4][4];
#pragma unroll
    for (int i = 0; i < 4; i++)
#pragma unroll
        for (int j = 0; j < 4; j++)
#pragma unroll
            for (int q = 0; q < 4; q++) acc[i][j][q] = 0.f;

    int c0 = tid, c1 = tid + 256;
    int r0c = c0 >> 2, cc0 = c0 & 3;
    int r1c = c1 >> 2, cc1 = c1 & 3;
    int ga0 = min(row0 + r0c, M - 1);
    int ga1 = min(row0 + r1c, M - 1);
    int gb0 = col0 + r0c;
    int gb1 = col0 + r1c;
    uint32_t so0 = (uint32_t)(r0c * ROWB + cc0 * 16);
    uint32_t so1 = (uint32_t)(r1c * ROWB + cc1 * 16);

#define PREFETCH(ks, buf) do {                                                   \
        int k0 = (ks) * BK;                                                      \
        uint32_t s0 = sb + (buf) * STAGEB + so0;                                 \
        uint32_t s1 = sb + (buf) * STAGEB + so1;                                 \
        cpa16(s0,              Ahi + (size_t)ga0 * FF + k0 + cc0 * 8);           \
        cpa16(s0 + TILEB,      Alo + (size_t)ga0 * FF + k0 + cc0 * 8);           \
        cpa16(s0 + 2 * TILEB,  Bh  + (size_t)gb0 * FF + k0 + cc0 * 8);           \
        cpa16(s1,              Ahi + (size_t)ga1 * FF + k0 + cc1 * 8);           \
        cpa16(s1 + TILEB,      Alo + (size_t)ga1 * FF + k0 + cc1 * 8);           \
        cpa16(s1 + 2 * TILEB,  Bh  + (size_t)gb1 * FF + k0 + cc1 * 8);           \
        cp_commit();                                                             \
    } while (0)

    int a_row  = wm + (lane & 15);
    int a_cch  = (lane >> 4) & 1;
    int b_row  = wn + (lane & 7) + ((lane >> 4) & 1) * 8;
    int b_cch  = ((lane >> 3) & 1) * 8;

    PREFETCH(0, 0);

    for (int ks = 0; ks < FF / BK; ks++) {
        int buf = ks & 1;
        if (ks < FF / BK - 1) { PREFETCH(ks + 1, buf ^ 1); cp_wait<1>(); }
        else                  { cp_wait<0>(); }
        __syncthreads();

        uint32_t base = sb + buf * STAGEB;
#pragma unroll
        for (int kc = 0; kc < 2; kc++) {
            int klocal = kc * 16;
            uint32_t ah[4][4], al[4][4];
#pragma unroll
            for (int i = 0; i < 4; i++) {
                uint32_t ad = base + (uint32_t)((a_row + i * 16) * ROWB
                                                + (klocal + a_cch * 8) * 2);
                ldm4(ah[i], ad);
                ldm4(al[i], ad + TILEB);
            }
            uint32_t bh[2][4];
#pragma unroll
            for (int jj = 0; jj < 2; jj++) {
                uint32_t bd = base + 2 * TILEB
                            + (uint32_t)((b_row + jj * 16) * ROWB
                                         + (klocal + b_cch) * 2);
                ldm4(bh[jj], bd);
            }
            // term 1: Ah * Bh (16 independent accumulators)
#pragma unroll
            for (int i = 0; i < 4; i++)
#pragma unroll
                for (int j = 0; j < 4; j++)
                    mma16816h(acc[i][j], ah[i], &bh[j >> 1][(j & 1) * 2]);
            // term 2: Al * Bh
#pragma unroll
            for (int i = 0; i < 4; i++)
#pragma unroll
                for (int j = 0; j < 4; j++)
                    mma16816h(acc[i][j], al[i], &bh[j >> 1][(j & 1) * 2]);
        }
        __syncthreads();
    }

    if (!EDGE) {
#pragma unroll
        for (int i = 0; i < 4; i++) {
            int r = row0 + wm + i * 16 + (lane >> 2);
            int cbase = col0 + wn + (lane & 3) * 2;
            if (r < M) {
                float* cp = C + (size_t)r * FF + cbase;
#pragma unroll
                for (int j = 0; j < 4; j++)
                    *(float2*)(cp + j * 8) = make_float2(acc[i][j][0], acc[i][j][1]);
            }
            if (r + 8 < M) {
                float* cp = C + (size_t)(r + 8) * FF + cbase;
#pragma unroll
                for (int j = 0; j < 4; j++)
                    *(float2*)(cp + j * 8) = make_float2(acc[i][j][2], acc[i][j][3]);
            }
        }
    } else {
        float s8[8], q8[8];
#pragma unroll
        for (int k = 0; k < 8; k++) { s8[k] = 0.f; q8[k] = 0.f; }
        int cbase = col0 + wn + (lane & 3) * 2;
#pragma unroll
        for (int i = 0; i < 4; i++) {
            int r  = row0 + wm + i * 16 + (lane >> 2);
            int r2 = r + 8;
            int sA = src[r],  dA = dst[r];
            int sB = src[r2], dB = dst[r2];
            float lf1 = 0.f, lb1 = 0.f, lf2 = 0.f, lb2 = 0.f;
#pragma unroll
            for (int j = 0; j < 4; j++) {
                int c = cbase + j * 8;
                float2 afv = *(const float2*)(af + c);
                float2 abv = *(const float2*)(ab + c);
                float2 xs = *(const float2*)(hWs + (size_t)sA * FF + c);
                float2 yd = *(const float2*)(hWd + (size_t)dA * FF + c);
                float v0 = acc[i][j][0] + xs.x + yd.x;
                float v1 = acc[i][j][1] + xs.y + yd.y;
                *(float2*)(C + (size_t)r * FF + c) = make_float2(v0, v1);
                lf1 += v0 * afv.x + v1 * afv.y;
                lb1 += v0 * abv.x + v1 * abv.y;
                s8[2 * j] += v0;       s8[2 * j + 1] += v1;
                q8[2 * j] += v0 * v0;  q8[2 * j + 1] += v1 * v1;
                float2 xs2 = *(const float2*)(hWs + (size_t)sB * FF + c);
                float2 yd2 = *(const float2*)(hWd + (size_t)dB * FF + c);
                float w0 = acc[i][j][2] + xs2.x + yd2.x;
                float w1 = acc[i][j][3] + xs2.y + yd2.y;
                *(float2*)(C + (size_t)r2 * FF + c) = make_float2(w0, w1);
                lf2 += w0 * afv.x + w1 * afv.y;
                lb2 += w0 * abv.x + w1 * abv.y;
                s8[2 * j] += w0;       s8[2 * j + 1] += w1;
                q8[2 * j] += w0 * w0;  q8[2 * j + 1] += w1 * w1;
            }
#pragma unroll
            for (int o = 1; o <= 2; o <<= 1) {
                lf1 += __shfl_xor_sync(0xffffffffu, lf1, o);
                lb1 += __shfl_xor_sync(0xffffffffu, lb1, o);
                lf2 += __shfl_xor_sync(0xffffffffu, lf2, o);
                lb2 += __shfl_xor_sync(0xffffffffu, lb2, o);
            }
            if ((lane & 3) == 0) {
                atomicAdd(&logf[r],  lf1);
                atomicAdd(&logb[r],  lb1);
                atomicAdd(&logf[r2], lf2);
                atomicAdd(&logb[r2], lb2);
            }
        }
#pragma unroll
        for (int k = 0; k < 8; k++) {
#pragma unroll
            for (int o = 4; o <= 16; o <<= 1) {
                s8[k] += __shfl_xor_sync(0xffffffffu, s8[k], o);
                q8[k] += __shfl_xor_sync(0xffffffffu, q8[k], o);
            }
        }
        if (lane < 4) {
            int cb = col0 + wn + lane * 2;
#pragma unroll
            for (int j = 0; j < 4; j++) {
                atomicAdd(&stats[cb + j * 8],          s8[2 * j]);
                atomicAdd(&stats[cb + j * 8 + 1],      s8[2 * j + 1]);
                atomicAdd(&stats[FF + cb + j * 8],     q8[2 * j]);
                atomicAdd(&stats[FF + cb + j * 8 + 1], q8[2 * j + 1]);
            }
        }
    }
#undef PREFETCH
}

__global__ void __launch_bounds__(256, 2)
gemm_edge(const __half* __restrict__ Ahi, const __half* __restrict__ Alo,
          const __half* __restrict__ Bh,
          float* __restrict__ C,
          const int* __restrict__ src, const int* __restrict__ dst,
          const float* __restrict__ hWs, const float* __restrict__ hWd,
          const float* __restrict__ af, const float* __restrict__ ab,
          float* __restrict__ logf, float* __restrict__ logb,
          float* __restrict__ stats)
{
    extern __shared__ __align__(128) char sm[];
    gemm_core<true>(Ahi, Alo, Bh, C, EE, blockIdx.y * 128, blockIdx.x * 128,
                    sm, src, dst, hWs, hWd, af, ab, logf, logb, stats);
}

// node GEMM, 2 types (Ws, Wd) — critical path
__global__ void __launch_bounds__(256, 2)
gemm_mma_multi2(const __half* __restrict__ Ahi, const __half* __restrict__ Alo,
                const __half* __restrict__ Bh0, float* C0, float* C1)
{
    extern __shared__ __align__(128) char sm[];
    int t = blockIdx.x >> 1;
    int col0 = (blockIdx.x & 1) * 128;
    size_t ws = (size_t)t * LL * FF * FF;
    float* C = (t == 0) ? C0 : C1;
    gemm_core<false>(Ahi, Alo, Bh0 + ws, C, NN, blockIdx.y * 128, col0,
                     sm, nullptr, nullptr, nullptr, nullptr, nullptr, nullptr,
                     nullptr, nullptr, nullptr);
}

// node GEMM, 3 types (Wself, Wf, Wb) — side stream
__global__ void __launch_bounds__(256, 2)
gemm_mma_multi3(const __half* __restrict__ Ahi, const __half* __restrict__ Alo,
                const __half* __restrict__ Bh0, float* C0, float* C1, float* C2)
{
    extern __shared__ __align__(128) char sm[];
    int t = blockIdx.x >> 1;
    int col0 = (blockIdx.x & 1) * 128;
    size_t ws = (size_t)t * LL * FF * FF;
    float* C = (t == 0) ? C0 : (t == 1) ? C1 : C2;
    gemm_core<false>(Ahi, Alo, Bh0 + ws, C, NN, blockIdx.y * 128, col0,
                     sm, nullptr, nullptr, nullptr, nullptr, nullptr, nullptr,
                     nullptr, nullptr, nullptr);
}

// ---------------- weight transpose + fp16 convert (all 6 types, one launch) -
__global__ void prep_w_all(const float* W0, const float* W1, const float* W2,
                           const float* W3, const float* W4, const float* W5,
                           __half* __restrict__ wh)
{
    int t   = blockIdx.x >> 10;
    int bl  = blockIdx.x & 1023;
    int l   = bl >> 8;
    int i   = (bl & 255) * 256 + threadIdx.x;
    int n = i >> 8, k = i & 255;
    const float* W = (t == 0) ? W0 : (t == 1) ? W1 : (t == 2) ? W2
                   : (t == 3) ? W3 : (t == 4) ? W4 : W5;
    size_t off = ((size_t)t * LL + l) * FF * FF;
    wh[off + i] = __float2half_rn(W[(size_t)l * FF * FF + (size_t)k * FF + n]);
}

// ---------------- fp32 -> fp16 hi/lo split (bulk) --------------------------
__global__ void split8(const float* __restrict__ x,
                       __half* __restrict__ hi, __half* __restrict__ lo,
                       size_t n8)
{
    for (size_t i = (size_t)blockIdx.x * blockDim.x + threadIdx.x; i < n8;
         i += (size_t)gridDim.x * blockDim.x) {
        float v[8];
        ld8(x + i * 8, v);
        uint4 uh, ul;
        split_pack(v, &uh, &ul);
        *(uint4*)(hi + i * 8) = uh;
        *(uint4*)(lo + i * 8) = ul;
    }
}

// ---------------- BN finalize ----------------------------------------------
__global__ void bnfin_kernel(float* stats, float inv_cnt) {
    int f = threadIdx.x;
    float mu  = stats[f] * inv_cnt;
    float var = stats[FF + f] * inv_cnt - mu * mu;
    stats[f]      = mu;
    stats[FF + f] = rsqrtf(var + BNEPS);
}

// ---------------- edge pass B: pure streaming -------------------------------
__global__ void __launch_bounds__(256)
edgeB_kernel(const float* __restrict__ etmp,
             __half* __restrict__ ehi, __half* __restrict__ elo,
             float* __restrict__ e_out,
             const float* __restrict__ stats,
             const float* __restrict__ ge, const float* __restrict__ be,
             int finalL)
{
    size_t i = (size_t)blockIdx.x * blockDim.x + threadIdx.x;
    const size_t NV = (size_t)EE * FF / 8;
    if (i >= NV) return;
    int c = ((int)i & 31) * 8;
    float t[8], ein[8], o[8];
    ld8(etmp + i * 8, t);
    uint4 uh = *(const uint4*)(ehi + i * 8);
    uint4 ul = *(const uint4*)(elo + i * 8);
    unpack8(uh, ul, ein);
#pragma unroll
    for (int j = 0; j < 8; j++) {
        float bn = (t[j] - stats[c + j]) * stats[FF + c + j] * ge[c + j] + be[c + j];
        o[j] = ein[j] + (bn > 0.f ? bn : 0.f);
    }
    if (finalL) {
        st8(e_out + i * 8, o);
    } else {
        uint4 nh, nl;
        split_pack(o, &nh, &nl);
        *(uint4*)(ehi + i * 8) = nh;
        *(uint4*)(elo + i * 8) = nl;
    }
}

// ---------------- node merge: local segment-max + gather aggregation --------
__global__ void __launch_bounds__(256)
nodeMerge_kernel(float* __restrict__ htmp,
                 const float* __restrict__ hWf, const float* __restrict__ hWb,
                 const float* __restrict__ logf, const float* __restrict__ logb,
                 const int* __restrict__ offI, const int* __restrict__ inEid,
                 const int* __restrict__ inSrc,
                 const int* __restrict__ offO, const int* __restrict__ outEid,
                 const int* __restrict__ outDst,
                 float* __restrict__ stats)
{
    int lane = threadIdx.x & 31;
    int gw = (blockIdx.x * blockDim.x + threadIdx.x) >> 5;
    int nw = (gridDim.x * blockDim.x) >> 5;
    int fb = lane * 8;

    float s[8], sq[8];
#pragma unroll
    for (int j = 0; j < 8; j++) { s[j] = 0.f; sq[j] = 0.f; }

    for (int n = gw; n < NN; n += nw) {
        float accf[8];
#pragma unroll
        for (int j = 0; j < 8; j++) accf[j] = 0.f;
        float denf = 0.f;
        {
            int b0 = offI[n], b1 = offI[n + 1];
            float mn = -1e30f;
            for (int k = b0 + lane; k < b1; k += 32) {
                float r = logf[inEid[k]];
                r = r > 0.f ? r : NEG_SLOPE * r;
                mn = fmaxf(mn, r);
            }
#pragma unroll
            for (int o = 16; o > 0; o >>= 1)
                mn = fmaxf(mn, __shfl_xor_sync(0xffffffffu, mn, o));
            for (int cb = b0; cb < b1; cb += 32) {
                int cnt = min(32, b1 - cb);
                float ex = 0.f; int si = 0;
                if (lane < cnt) {
                    int k = cb + lane;
                    si = inSrc[k];
                    float r = logf[inEid[k]];
                    r = r > 0.f ? r : NEG_SLOPE * r;
                    ex = expf(r - mn);
                }
                for (int j = 0; j < cnt; j++) {
                    float e  = __shfl_sync(0xffffffffu, ex, j);
                    int   s_ = __shfl_sync(0xffffffffu, si, j);
                    float w[8];
                    ld8(hWf + (size_t)s_ * FF + fb, w);
                    denf += e;
#pragma unroll
                    for (int q = 0; q < 8; q++) accf[q] += e * w[q];
                }
            }
        }
        float accb[8];
#pragma unroll
        for (int j = 0; j < 8; j++) accb[j] = 0.f;
        float denb = 0.f;
        {
            int b0 = offO[n], b1 = offO[n + 1];
            float mn = -1e30f;
            for (int k = b0 + lane; k < b1; k += 32) {
                float r = logb[outEid[k]];
                r = r > 0.f ? r : NEG_SLOPE * r;
                mn = fmaxf(mn, r);
            }
#pragma unroll
            for (int o = 16; o > 0; o >>= 1)
                mn = fmaxf(mn, __shfl_xor_sync(0xffffffffu, mn, o));
            for (int cb = b0; cb < b1; cb += 32) {
                int cnt = min(32, b1 - cb);
                float ex = 0.f; int di = 0;
                if (lane < cnt) {
                    int k = cb + lane;
                    di = outDst[k];
                    float r = logb[outEid[k]];
                    r = r > 0.f ? r : NEG_SLOPE * r;
                    ex = expf(r - mn);
                }
                for (int j = 0; j < cnt; j++) {
                    float e  = __shfl_sync(0xffffffffu, ex, j);
                    int   d_ = __shfl_sync(0xffffffffu, di, j);
                    float w[8];
                    ld8(hWb + (size_t)d_ * FF + fb, w);
                    denb += e;
#pragma unroll
                    for (int q = 0; q < 8; q++) accb[q] += e * w[q];
                }
            }
        }
        float rf = 1.f / (denf + 1e-9f);
        float rb = 1.f / (denb + 1e-9f);
        float v[8];
        float* ph = htmp + (size_t)n * FF + fb;
        ld8(ph, v);
#pragma unroll
        for (int j = 0; j < 8; j++) {
            v[j] = v[j] + accf[j] * rf + accb[j] * rb;
            s[j]  += v[j];
            sq[j] += v[j] * v[j];
        }
        st8(ph, v);
    }
#pragma unroll
    for (int j = 0; j < 8; j++) {
        atomicAdd(&stats[fb + j], s[j]);
        atomicAdd(&stats[FF + fb + j], sq[j]);
    }
}

// ---------------- node pass B ----------------------------------------------
__global__ void __launch_bounds__(256)
nodeB_kernel(const float* __restrict__ htmp, const float* __restrict__ h_in,
             float* __restrict__ h_out, const float* __restrict__ stats,
             const float* __restrict__ gh, const float* __restrict__ bh,
             __half* __restrict__ hhi, __half* __restrict__ hlo,
             int wsplit)
{
    int i = blockIdx.x * blockDim.x + threadIdx.x;
    const int NV = NN * FF / 8;
    if (i >= NV) return;
    int c = (i & 31) * 8;
    float t[8], hv[8], o[8];
    ld8(htmp + (size_t)i * 8, t);
    ld8(h_in + (size_t)i * 8, hv);
#pragma unroll
    for (int j = 0; j < 8; j++) {
        float bn = (t[j] - stats[c + j]) * stats[FF + c + j] * gh[c + j] + bh[c + j];
        o[j] = hv[j] + (bn > 0.f ? bn : 0.f);
    }
    st8(h_out + (size_t)i * 8, o);
    if (wsplit) {
        uint4 uh, ul;
        split_pack(o, &uh, &ul);
        *(uint4*)(hhi + (size_t)i * 8) = uh;
        *(uint4*)(hlo + (size_t)i * 8) = ul;
    }
}

// ---------------- launch ---------------------------------------------------
extern "C" void kernel_launch(void* const* d_in, const int* in_sizes, int n_in,
                              void* d_out, int out_size)
{
    (void)in_sizes; (void)n_in; (void)out_size;
    const float* h0    = (const float*)d_in[0];
    const float* e0    = (const float*)d_in[1];
    const int*   src   = (const int*)d_in[2];
    const int*   dst   = (const int*)d_in[3];
    const float* We    = (const float*)d_in[4];
    const float* Ws    = (const float*)d_in[5];
    const float* Wd    = (const float*)d_in[6];
    const float* Wself = (const float*)d_in[7];
    const float* Wf    = (const float*)d_in[8];
    const float* Wb    = (const float*)d_in[9];
    const float* att_f = (const float*)d_in[10];
    const float* att_b = (const float*)d_in[11];
    const float* g_e   = (const float*)d_in[12];
    const float* b_e   = (const float*)d_in[13];
    const float* g_h   = (const float*)d_in[14];
    const float* b_h   = (const float*)d_in[15];

    float* outh = (float*)d_out;
    float* oute = outh + (size_t)NN * FF;

    float *etmp, *hWs, *hWd, *hWf, *hWb, *htmp;
    float *logf, *logb, *stE, *stH;
    __half *ehi, *elo, *hhi, *hlo, *wth;
    int *degI, *degO, *offI, *offO, *curI, *curO, *inEid, *inSrc, *outEid, *outDst;
    cudaGetSymbolAddress((void**)&etmp, g_etmp);
    cudaGetSymbolAddress((void**)&hWs,  g_hWs);
    cudaGetSymbolAddress((void**)&hWd,  g_hWd);
    cudaGetSymbolAddress((void**)&hWf,  g_hWf);
    cudaGetSymbolAddress((void**)&hWb,  g_hWb);
    cudaGetSymbolAddress((void**)&htmp, g_htmp);
    cudaGetSymbolAddress((void**)&logf, g_logf);
    cudaGetSymbolAddress((void**)&logb, g_logb);
    cudaGetSymbolAddress((void**)&stE,  g_statsE);
    cudaGetSymbolAddress((void**)&stH,  g_statsH);
    cudaGetSymbolAddress((void**)&ehi,  g_ehi);
    cudaGetSymbolAddress((void**)&elo,  g_elo);
    cudaGetSymbolAddress((void**)&hhi,  g_hhi);
    cudaGetSymbolAddress((void**)&hlo,  g_hlo);
    cudaGetSymbolAddress((void**)&wth,  g_wth);
    cudaGetSymbolAddress((void**)&degI, g_degI);
    cudaGetSymbolAddress((void**)&degO, g_degO);
    cudaGetSymbolAddress((void**)&offI, g_offI);
    cudaGetSymbolAddress((void**)&offO, g_offO);
    cudaGetSymbolAddress((void**)&curI, g_curI);
    cudaGetSymbolAddress((void**)&curO, g_curO);
    cudaGetSymbolAddress((void**)&inEid,  g_inEid);
    cudaGetSymbolAddress((void**)&inSrc,  g_inSrc);
    cudaGetSymbolAddress((void**)&outEid, g_outEid);
    cudaGetSymbolAddress((void**)&outDst, g_outDst);

    cudaFuncSetAttribute((const void*)gemm_edge,
                         cudaFuncAttributeMaxDynamicSharedMemorySize, GEMM_SMEM);
    cudaFuncSetAttribute((const void*)gemm_mma_multi2,
                         cudaFuncAttributeMaxDynamicSharedMemorySize, GEMM_SMEM);
    cudaFuncSetAttribute((const void*)gemm_mma_multi3,
                         cudaFuncAttributeMaxDynamicSharedMemorySize, GEMM_SMEM);

    const size_t WM = (size_t)FF * FF;

    // side stream + events for capture-legal fork/join overlap
    cudaStream_t side;
    cudaStreamCreateWithFlags(&side, cudaStreamNonBlocking);
    cudaEvent_t evF, evJ, evM, evB;
    cudaEventCreateWithFlags(&evF, cudaEventDisableTiming);
    cudaEventCreateWithFlags(&evJ, cudaEventDisableTiming);
    cudaEventCreateWithFlags(&evM, cudaEventDisableTiming);
    cudaEventCreateWithFlags(&evB, cudaEventDisableTiming);

    // ---- prep: fork the big e-split onto the side stream ----
    cudaEventRecord(evF, 0);
    cudaStreamWaitEvent(side, evF, 0);
    split8<<<8192, 256, 0, side>>>(e0, ehi, elo, (size_t)EE * FF / 8);
    cudaEventRecord(evJ, side);

    prep_w_all<<<6 * 1024, 256>>>(We, Ws, Wd, Wself, Wf, Wb, wth);
    split8<<<4096, 256>>>(h0, hhi, hlo, (size_t)NN * FF / 8);
    fill_u<<<64, 256>>>((unsigned*)degI, NN, 0u);
    fill_u<<<64, 256>>>((unsigned*)degO, NN, 0u);
    hist_kernel<<<1024, 256>>>(src, dst, degI, degO);
    scan_kernel<<<1, 1024>>>(degI, degO, offI, offO, curI, curO);
    scatter_kernel<<<1024, 256>>>(src, dst, curI, curO, inEid, inSrc, outEid, outDst);

    dim3 gEdge(2, EE / 128);           // (2, 6250)
    dim3 gM2(4, (NN + 127) / 128);     // 2 types x 2 col blocks
    dim3 gM3(6, (NN + 127) / 128);     // 3 types x 2 col blocks

    for (int l = 0; l < LL; l++) {
        const float* hcur = l ? outh : h0;
        size_t wo = (size_t)l * WM;
        float* stEp = stE + (size_t)(l & 1) * 2 * FF;   // parity buffer

        init_layer<<<2048, 256>>>(logf, logb, stEp, stH);

        // critical-path node GEMM: Ws, Wd only (edge epilogue consumes these)
        gemm_mma_multi2<<<gM2, 256, GEMM_SMEM>>>(hhi, hlo,
            wth + 1 * LL * WM + wo, hWs, hWd);

        // fork: Wself/Wf/Wb GEMM on side stream
        cudaEventRecord(evF, 0);
        cudaStreamWaitEvent(side, evF, 0);
        gemm_mma_multi3<<<gM3, 256, GEMM_SMEM, side>>>(hhi, hlo,
            wth + 3 * LL * WM + wo, htmp, hWf, hWb);
        cudaEventRecord(evM, side);

        // join previous side-stream edgeB (ehi/elo ready; etmp free to overwrite)
        cudaStreamWaitEvent(0, evJ, 0);

        // edge GEMM with fused edgeA epilogue
        gemm_edge<<<gEdge, 256, GEMM_SMEM>>>(ehi, elo,
            wth + 0 * LL * WM + wo, etmp,
            src, dst, hWs, hWd,
            att_f + (size_t)l * FF, att_b + (size_t)l * FF,
            logf, logb, stEp);

        int wsplit = (l < LL - 1) ? 1 : 0;
        int finalL = (l == LL - 1) ? 1 : 0;

        bnfin_kernel<<<1, FF>>>(stEp, 1.f / EE);

        // fork edgeB onto side stream (after bnfinE): overlaps node chain
        cudaEventRecord(evB, 0);
        cudaStreamWaitEvent(side, evB, 0);
        edgeB_kernel<<<(int)(((size_t)EE * FF / 8 + 255) / 256), 256, 0, side>>>(
            etmp, ehi, elo, oute, stEp,
            g_e + (size_t)l * FF, b_e + (size_t)l * FF, finalL);
        cudaEventRecord(evJ, side);

        // join multi3 (htmp/hWf/hWb ready) before nodeMerge
        cudaStreamWaitEvent(0, evM, 0);

        nodeMerge_kernel<<<768, 256>>>(htmp, hWf, hWb, logf, logb,
                                       offI, inEid, inSrc, offO, outEid, outDst, stH);
        bnfin_kernel<<<1, FF>>>(stH, 1.f / NN);
        nodeB_kernel<<<(NN * FF / 8 + 255) / 256, 256>>>(
            htmp, hcur, outh, stH, g_h + (size_t)l * FF, b_h + (size_t)l * FF,
            hhi, hlo, wsplit);
    }

    // final join: last edgeB (writes d_out's e section) must complete
    cudaStreamWaitEvent(0, evJ, 0);

    cudaEventDestroy(evF);
    cudaEventDestroy(evJ);
    cudaEventDestroy(evM);
    cudaEventDestroy(evB);
    cudaStreamDestroy(side);
}